// round 4
// baseline (speedup 1.0000x reference)
#include <cuda_runtime.h>
#include <cstdint>

#define N_ITEMS 16384
#define N_NODES 8192
#define HD 128
#define DOUT 64
#define NEDGE 524288
#define IMASK (N_ITEMS - 1)

// ---------------- scratch (device globals; no allocation allowed) ----------
__device__ __align__(128) float g_h[N_ITEMS * HD];     // x @ W_gat
__device__ __align__(128) float g_gat[N_ITEMS * HD];   // GAT output (+b_gat)
__device__ __align__(128) float g_g2[N_ITEMS * HD];    // gat_out @ W_etn
__device__ __align__(128) float g_y[N_NODES * HD];     // H @ g2
__device__ __align__(128) float g_ssrc[N_ITEMS];
__device__ __align__(128) float g_sdst[N_ITEMS];
__device__ int g_cnt[N_ITEMS];
__device__ int g_off[N_ITEMS + 1];
__device__ int g_pos[N_ITEMS];
__device__ int g_esrc[NEDGE];

__device__ __forceinline__ float leaky(float v) { return v >= 0.f ? v : 0.2f * v; }

__device__ __forceinline__ uint32_t f2tf(float x) {
    uint32_t r;
    asm("cvt.rna.tf32.f32 %0, %1;" : "=r"(r) : "f"(x));
    return r;
}
__device__ __forceinline__ void cp16(uint32_t s, const void* g) {
    asm volatile("cp.async.cg.shared.global [%0], [%1], 16;\n" ::"r"(s), "l"(g));
}

// ======================================================================
// tf32 GEMM: C[M,128] = A[M,K] @ B[K,128].  grid.x = M/64, block = 128.
// mode 0: A=x(ext),    B=W_gat(ext), C=g_h
// mode 1: A=g_gat,     B=W_etn(ext), C=g_g2
// mode 2: A=H(ext),    B=g_g2,       C=g_y
// ======================================================================
__global__ void __launch_bounds__(128) gemm_tf32_kernel(
    const float* __restrict__ Aext, const float* __restrict__ Bext,
    int K, int lda, int mode)
{
    __shared__ float As[2][64][32];    // 16 KB, XOR-swizzled
    __shared__ float Bs[2][32][128];   // 32 KB, XOR-swizzled

    const float* A = (mode == 1) ? g_gat : Aext;
    const float* B = (mode == 2) ? g_g2 : Bext;
    float* C = (mode == 0) ? g_h : (mode == 1 ? g_g2 : g_y);

    const int tid = threadIdx.x;
    const int lane = tid & 31, wid = tid >> 5;   // 4 warps: warp wid owns cols wid*32..+31
    const int grp = lane >> 2, th4 = lane & 3;
    const int m0 = blockIdx.x * 64;

    float c[4][4][4];
#pragma unroll
    for (int i = 0; i < 4; i++)
#pragma unroll
        for (int j = 0; j < 4; j++)
#pragma unroll
            for (int k = 0; k < 4; k++) c[i][j][k] = 0.f;

    const int KT = K >> 5;

    auto load_tile = [&](int kt, int buf) {
        const int kk = kt * 32;
#pragma unroll
        for (int j = 0; j < 4; j++) {          // A tile: 64x32 f32 = 512 x 16B
            int i = tid + j * 128;
            int row = i >> 3, ch = i & 7;
            uint32_t s = (uint32_t)__cvta_generic_to_shared(
                &As[buf][row][(ch ^ (row & 7)) * 4]);
            cp16(s, A + (size_t)(m0 + row) * lda + kk + ch * 4);
        }
#pragma unroll
        for (int j = 0; j < 8; j++) {          // B tile: 32x128 f32 = 1024 x 16B
            int i = tid + j * 128;
            int row = i >> 5, ch = i & 31;
            uint32_t s = (uint32_t)__cvta_generic_to_shared(
                &Bs[buf][row][(ch ^ ((row & 3) << 1)) * 4]);
            cp16(s, B + (size_t)(kk + row) * 128 + ch * 4);
        }
        asm volatile("cp.async.commit_group;");
    };

    load_tile(0, 0);
    int buf = 0;
    for (int kt = 0; kt < KT; ++kt) {
        if (kt + 1 < KT) {
            load_tile(kt + 1, buf ^ 1);
            asm volatile("cp.async.wait_group 1;");
        } else {
            asm volatile("cp.async.wait_group 0;");
        }
        __syncthreads();
#pragma unroll
        for (int k8 = 0; k8 < 4; k8++) {
            uint32_t a[4][4];
#pragma unroll
            for (int mt = 0; mt < 4; mt++) {
                int r0 = mt * 16 + grp;
                int r1 = r0 + 8;
                int sw = grp;  // (r&7) == grp for both r0, r1
                a[mt][0] = f2tf(As[buf][r0][((2 * k8) ^ sw) * 4 + th4]);
                a[mt][1] = f2tf(As[buf][r1][((2 * k8) ^ sw) * 4 + th4]);
                a[mt][2] = f2tf(As[buf][r0][((2 * k8 + 1) ^ sw) * 4 + th4]);
                a[mt][3] = f2tf(As[buf][r1][((2 * k8 + 1) ^ sw) * 4 + th4]);
            }
#pragma unroll
            for (int nt = 0; nt < 4; nt++) {
                int col = wid * 32 + nt * 8 + grp;
                int idx = ((col >> 2) ^ (th4 << 1)) * 4 + (col & 3);
                uint32_t b0 = f2tf(Bs[buf][k8 * 8 + th4][idx]);
                uint32_t b1 = f2tf(Bs[buf][k8 * 8 + th4 + 4][idx]);
#pragma unroll
                for (int mt = 0; mt < 4; mt++) {
                    asm volatile(
                        "mma.sync.aligned.m16n8k8.row.col.f32.tf32.tf32.f32 "
                        "{%0,%1,%2,%3},{%4,%5,%6,%7},{%8,%9},{%0,%1,%2,%3};"
                        : "+f"(c[mt][nt][0]), "+f"(c[mt][nt][1]),
                          "+f"(c[mt][nt][2]), "+f"(c[mt][nt][3])
                        : "r"(a[mt][0]), "r"(a[mt][1]), "r"(a[mt][2]), "r"(a[mt][3]),
                          "r"(b0), "r"(b1));
                }
            }
        }
        __syncthreads();
        buf ^= 1;
    }

#pragma unroll
    for (int mt = 0; mt < 4; mt++) {
#pragma unroll
        for (int nt = 0; nt < 4; nt++) {
            int row = m0 + mt * 16 + grp;
            int col = wid * 32 + nt * 8 + 2 * th4;
            *(float2*)&C[(size_t)row * 128 + col] =
                make_float2(c[mt][nt][0], c[mt][nt][1]);
            *(float2*)&C[(size_t)(row + 8) * 128 + col] =
                make_float2(c[mt][nt][2], c[mt][nt][3]);
        }
    }
}

// ----------------- attention scores: s_src = h.a_src, s_dst = h.a_dst ------
__global__ void __launch_bounds__(256) dots_kernel(const float* __restrict__ a_src,
                                                   const float* __restrict__ a_dst)
{
    int warp = (blockIdx.x * blockDim.x + threadIdx.x) >> 5;
    if (warp >= N_ITEMS) return;
    int lane = threadIdx.x & 31;
    float4 hv = *(const float4*)&g_h[(size_t)warp * 128 + lane * 4];
    float4 s4 = *(const float4*)&a_src[lane * 4];
    float4 d4 = *(const float4*)&a_dst[lane * 4];
    float s1 = hv.x * s4.x + hv.y * s4.y + hv.z * s4.z + hv.w * s4.w;
    float s2 = hv.x * d4.x + hv.y * d4.y + hv.z * d4.z + hv.w * d4.w;
#pragma unroll
    for (int o = 16; o; o >>= 1) {
        s1 += __shfl_xor_sync(0xffffffffu, s1, o);
        s2 += __shfl_xor_sync(0xffffffffu, s2, o);
    }
    if (lane == 0) { g_ssrc[warp] = s1; g_sdst[warp] = s2; }
}

// ----------------- CSR build (edge_index is int32: jax x64 disabled) --------
__global__ void zero_cnt_kernel()
{
    for (int i = blockIdx.x * blockDim.x + threadIdx.x; i < N_ITEMS;
         i += gridDim.x * blockDim.x)
        g_cnt[i] = 0;
}

__global__ void count_kernel(const int* __restrict__ ei)
{
    int e = blockIdx.x * blockDim.x + threadIdx.x;
    if (e < NEDGE) atomicAdd(&g_cnt[ei[NEDGE + e] & IMASK], 1);
}

__global__ void __launch_bounds__(1024) scan_kernel()
{
    __shared__ int ssum[1024];
    int t = threadIdx.x;
    int base = t * 16;
    int loc[16];
    int s = 0;
#pragma unroll
    for (int i = 0; i < 16; i++) { loc[i] = g_cnt[base + i]; s += loc[i]; }
    ssum[t] = s;
    __syncthreads();
    for (int d = 1; d < 1024; d <<= 1) {
        int v = (t >= d) ? ssum[t - d] : 0;
        __syncthreads();
        ssum[t] += v;
        __syncthreads();
    }
    int run = t ? ssum[t - 1] : 0;
#pragma unroll
    for (int i = 0; i < 16; i++) {
        g_off[base + i] = run;
        g_pos[base + i] = run;
        run += loc[i];
    }
    if (t == 1023) g_off[N_ITEMS] = run;
}

__global__ void scatter_kernel(const int* __restrict__ ei)
{
    int e = blockIdx.x * blockDim.x + threadIdx.x;
    if (e >= NEDGE) return;
    int d = ei[NEDGE + e] & IMASK;
    int p = atomicAdd(&g_pos[d], 1);
    g_esrc[p] = ei[e] & IMASK;
}

// ----------------- GAT gather: warp per target node -------------------------
__global__ void __launch_bounds__(256) gather_kernel(const float* __restrict__ b_gat)
{
    int node = (blockIdx.x * blockDim.x + threadIdx.x) >> 5;
    if (node >= N_ITEMS) return;
    int lane = threadIdx.x & 31;

    float sd = g_sdst[node];
    // self-loop
    float w = __expf(leaky(g_ssrc[node] + sd));
    float denom = w;
    float4 hv = *(const float4*)&g_h[(size_t)node * 128 + lane * 4];
    float4 acc = make_float4(w * hv.x, w * hv.y, w * hv.z, w * hv.w);

    int j = g_off[node], end = g_off[node + 1];
    int s_next = (j < end) ? g_esrc[j] : 0;
    for (; j < end; ++j) {
        int s = s_next;
        if (j + 1 < end) s_next = g_esrc[j + 1];
        float ss = g_ssrc[s];
        float4 hv2 = *(const float4*)&g_h[(size_t)s * 128 + lane * 4];
        float w2 = __expf(leaky(ss + sd));
        denom += w2;
        acc.x += w2 * hv2.x; acc.y += w2 * hv2.y;
        acc.z += w2 * hv2.z; acc.w += w2 * hv2.w;
    }
    float inv = 1.0f / denom;
    float4 bg = *(const float4*)&b_gat[lane * 4];
    float4 outv = make_float4(acc.x * inv + bg.x, acc.y * inv + bg.y,
                              acc.z * inv + bg.z, acc.w * inv + bg.w);
    *(float4*)&g_gat[(size_t)node * 128 + lane * 4] = outv;
}

// ----------------- epilogue: out = leaky(Y + b_etn) @ W_lin ------------------
__global__ void __launch_bounds__(256) final_kernel(const float* __restrict__ b_etn,
                                                    const float* __restrict__ W_lin,
                                                    float* __restrict__ out)
{
    __shared__ float Wl[128 * 64];   // 32 KB
    __shared__ float yrow[8][128];
    int tid = threadIdx.x;
    for (int i = tid; i < 128 * 64; i += 256) Wl[i] = W_lin[i];
    __syncthreads();

    int warp = tid >> 5, lane = tid & 31;
    int r = blockIdx.x * 8 + warp;
    if (r >= N_NODES) return;

    float4 yv = *(const float4*)&g_y[(size_t)r * 128 + lane * 4];
    float4 bv = *(const float4*)&b_etn[lane * 4];
    yrow[warp][lane * 4 + 0] = leaky(yv.x + bv.x);
    yrow[warp][lane * 4 + 1] = leaky(yv.y + bv.y);
    yrow[warp][lane * 4 + 2] = leaky(yv.z + bv.z);
    yrow[warp][lane * 4 + 3] = leaky(yv.w + bv.w);
    __syncwarp();

    float acc0 = 0.f, acc1 = 0.f;
#pragma unroll
    for (int k = 0; k < 128; k++) {
        float yk = yrow[warp][k];
        acc0 += yk * Wl[k * 64 + lane];
        acc1 += yk * Wl[k * 64 + lane + 32];
    }
    out[(size_t)r * 64 + lane] = acc0;
    out[(size_t)r * 64 + lane + 32] = acc1;
}

// ======================================================================
extern "C" void kernel_launch(void* const* d_in, const int* in_sizes, int n_in,
                              void* d_out, int out_size)
{
    const float* x      = (const float*)d_in[0];
    const float* Hm     = (const float*)d_in[1];
    const int*   ei     = (const int*)d_in[2];     // int32 (jax x64 disabled)
    const float* W_gat  = (const float*)d_in[3];
    const float* a_src  = (const float*)d_in[4];
    const float* a_dst  = (const float*)d_in[5];
    const float* b_gat  = (const float*)d_in[6];
    const float* W_etn  = (const float*)d_in[7];
    const float* b_etn  = (const float*)d_in[8];
    const float* W_lin  = (const float*)d_in[9];
    float* out = (float*)d_out;

    // 1. h = x @ W_gat                       [16384,128]
    gemm_tf32_kernel<<<N_ITEMS / 64, 128>>>(x, W_gat, 128, 128, 0);
    // 2. attention dot products
    dots_kernel<<<(N_ITEMS * 32) / 256, 256>>>(a_src, a_dst);
    // 3. CSR by dst
    zero_cnt_kernel<<<64, 256>>>();
    count_kernel<<<NEDGE / 256, 256>>>(ei);
    scan_kernel<<<1, 1024>>>();
    scatter_kernel<<<NEDGE / 256, 256>>>(ei);
    // 4. segment softmax + weighted gather (+ b_gat)
    gather_kernel<<<(N_ITEMS * 32) / 256, 256>>>(b_gat);
    // 5. g2 = gat_out @ W_etn                [16384,128]
    gemm_tf32_kernel<<<N_ITEMS / 64, 128>>>(nullptr, W_etn, 128, 128, 1);
    // 6. Y = H @ g2                          [8192,128]  (the big one)
    gemm_tf32_kernel<<<N_NODES / 64, 128>>>(Hm, nullptr, N_ITEMS, N_ITEMS, 2);
    // 7. out = leaky(Y + b_etn) @ W_lin      [8192,64]
    final_kernel<<<N_NODES / 8, 256>>>(b_etn, W_lin, out);
}

// round 6
// speedup vs baseline: 1.2144x; 1.2144x over previous
#include <cuda_runtime.h>
#include <cstdint>

#define N_ITEMS 16384
#define N_NODES 8192
#define HD 128
#define DOUT 64
#define NEDGE 524288
#define IMASK (N_ITEMS - 1)

// ---------------- scratch (device globals; no allocation allowed) ----------
__device__ __align__(128) float g_h[N_ITEMS * HD];     // x @ W_gat
__device__ __align__(128) float g_gat[N_ITEMS * HD];   // GAT output (+b_gat)
__device__ __align__(128) float g_g2t[HD * N_ITEMS];   // (gat@W_etn)^T, tf32-rounded bits
__device__ __align__(128) float g_y[N_NODES * HD];     // partial K[0:8192)
__device__ __align__(128) float g_y2[N_NODES * HD];    // partial K[8192:16384)
__device__ __align__(128) float g_ssrc[N_ITEMS];
__device__ __align__(128) float g_sdst[N_ITEMS];
__device__ int g_cnt[N_ITEMS];
__device__ int g_off[N_ITEMS + 1];
__device__ int g_pos[N_ITEMS];
__device__ int g_esrc[NEDGE];

__device__ __forceinline__ float leaky(float v) { return v >= 0.f ? v : 0.2f * v; }

__device__ __forceinline__ uint32_t f2tf(float x) {
    uint32_t r;
    asm("cvt.rna.tf32.f32 %0, %1;" : "=r"(r) : "f"(x));
    return r;
}
__device__ __forceinline__ void cp16(uint32_t s, const void* g) {
    asm volatile("cp.async.cg.shared.global [%0], [%1], 16;\n" ::"r"(s), "l"(g));
}

// ======================================================================
// Big GEMM: Y[8192,128] = H[8192,16384] @ g2[16384,128], split-K x2.
// grid = 128 (64 m-tiles x 2 k-splits), block = 256 (8 warps, warp tile 64x32)
// A fed as raw f32 (HW tf32 truncation); B pre-rounded tf32 bits in g_g2t.
// ======================================================================
#define BKC 32
#define BSTG 32768            // A(16KB) + B(16KB) per stage
#define BNST 4
#define SMEM_BIG (1024 + BNST * BSTG)
#define BKT 256               // 8192 / 32 stages

__global__ void __launch_bounds__(256) bigmm_kernel(const float* __restrict__ A)
{
    extern __shared__ char smraw[];
    char* sm = (char*)(((uintptr_t)smraw + 1023) & ~(uintptr_t)1023);

    const int tid = threadIdx.x;
    const int lane = tid & 31, wid = tid >> 5;
    const int wm = wid & 1, wn = wid >> 1;      // warp tile: rows wm*64.., cols wn*32..
    const int grp = lane >> 2, th4 = lane & 3;
    const int mtile = blockIdx.x >> 1, ks = blockIdx.x & 1;
    const int m0 = mtile * 128;
    const int k0 = ks * 8192;

    float c[4][4][4];
#pragma unroll
    for (int i = 0; i < 4; i++)
#pragma unroll
        for (int j = 0; j < 4; j++)
#pragma unroll
            for (int k = 0; k < 4; k++) c[i][j][k] = 0.f;

    auto load_tile = [&](int t) {
        char* as = sm + (t & 3) * BSTG;
        char* bs = as + 16384;
        const int kb = k0 + t * BKC;
#pragma unroll
        for (int i = 0; i < 4; i++) {       // A: 128 rows x 32 f32
            int id = tid + i * 256;
            int row = id >> 3, ch = id & 7;
            cp16((uint32_t)__cvta_generic_to_shared(as + row * 128 + ((ch ^ (row & 7)) << 4)),
                 A + (size_t)(m0 + row) * 16384 + kb + ch * 4);
        }
#pragma unroll
        for (int i = 0; i < 4; i++) {       // B: 128 rows (n) x 32 f32 (k)
            int id = tid + i * 256;
            int row = id >> 3, ch = id & 7;
            cp16((uint32_t)__cvta_generic_to_shared(bs + row * 128 + ((ch ^ (row & 7)) << 4)),
                 g_g2t + (size_t)row * 16384 + kb + ch * 4);
        }
        asm volatile("cp.async.commit_group;");
    };

    load_tile(0);
    load_tile(1);
    load_tile(2);

    for (int t = 0; t < BKT; ++t) {
        if (t + 3 < BKT) load_tile(t + 3);
        else asm volatile("cp.async.commit_group;");
        asm volatile("cp.async.wait_group 3;");
        __syncthreads();

        const uint32_t* as = (const uint32_t*)(sm + (t & 3) * BSTG);
        const uint32_t* bs = as + 4096;
#pragma unroll
        for (int k8 = 0; k8 < 4; k8++) {
            const int c0 = (2 * k8) ^ grp, c1 = (2 * k8 + 1) ^ grp;
            uint32_t a[4][4], b[4][2];
#pragma unroll
            for (int mt = 0; mt < 4; mt++) {
                int r0 = wm * 64 + mt * 16 + grp;
                a[mt][0] = as[r0 * 32 + c0 * 4 + th4];
                a[mt][1] = as[(r0 + 8) * 32 + c0 * 4 + th4];
                a[mt][2] = as[r0 * 32 + c1 * 4 + th4];
                a[mt][3] = as[(r0 + 8) * 32 + c1 * 4 + th4];
            }
#pragma unroll
            for (int nt = 0; nt < 4; nt++) {
                int cn = wn * 32 + nt * 8 + grp;
                b[nt][0] = bs[cn * 32 + c0 * 4 + th4];
                b[nt][1] = bs[cn * 32 + c1 * 4 + th4];
            }
#pragma unroll
            for (int nt = 0; nt < 4; nt++)
#pragma unroll
                for (int mt = 0; mt < 4; mt++) {
                    asm volatile(
                        "mma.sync.aligned.m16n8k8.row.col.f32.tf32.tf32.f32 "
                        "{%0,%1,%2,%3},{%4,%5,%6,%7},{%8,%9},{%0,%1,%2,%3};"
                        : "+f"(c[mt][nt][0]), "+f"(c[mt][nt][1]),
                          "+f"(c[mt][nt][2]), "+f"(c[mt][nt][3])
                        : "r"(a[mt][0]), "r"(a[mt][1]), "r"(a[mt][2]), "r"(a[mt][3]),
                          "r"(b[nt][0]), "r"(b[nt][1]));
                }
        }
        __syncthreads();
    }

    float* Y = ks ? g_y2 : g_y;
#pragma unroll
    for (int mt = 0; mt < 4; mt++) {
#pragma unroll
        for (int nt = 0; nt < 4; nt++) {
            int row = m0 + wm * 64 + mt * 16 + grp;
            int col = wn * 32 + nt * 8 + 2 * th4;
            *(float2*)&Y[(size_t)row * 128 + col] =
                make_float2(c[mt][nt][0], c[mt][nt][1]);
            *(float2*)&Y[(size_t)(row + 8) * 128 + col] =
                make_float2(c[mt][nt][2], c[mt][nt][3]);
        }
    }
}

// ======================================================================
// small tf32 GEMM (mma.sync): C[M,128] = A[M,K] @ B[K,128], K=128
// mode 0: A=x, B=W_gat -> g_h
// mode 1: A=g_gat, B=W_etn -> g_g2t (transposed, tf32-rounded bits)
// ======================================================================
__global__ void __launch_bounds__(128) gemm_tf32_kernel(
    const float* __restrict__ Aext, const float* __restrict__ Bext, int mode)
{
    __shared__ float As[2][64][32];
    __shared__ float Bs[2][32][128];

    const float* A = (mode == 1) ? g_gat : Aext;
    const float* B = Bext;

    const int tid = threadIdx.x;
    const int lane = tid & 31, wid = tid >> 5;
    const int grp = lane >> 2, th4 = lane & 3;
    const int m0 = blockIdx.x * 64;

    float c[4][4][4];
#pragma unroll
    for (int i = 0; i < 4; i++)
#pragma unroll
        for (int j = 0; j < 4; j++)
#pragma unroll
            for (int k = 0; k < 4; k++) c[i][j][k] = 0.f;

    auto load_tile = [&](int kt, int buf) {
        const int kk = kt * 32;
#pragma unroll
        for (int j = 0; j < 4; j++) {
            int i = tid + j * 128;
            int row = i >> 3, ch = i & 7;
            uint32_t s = (uint32_t)__cvta_generic_to_shared(
                &As[buf][row][(ch ^ (row & 7)) * 4]);
            cp16(s, A + (size_t)(m0 + row) * 128 + kk + ch * 4);
        }
#pragma unroll
        for (int j = 0; j < 8; j++) {
            int i = tid + j * 128;
            int row = i >> 5, ch = i & 31;
            uint32_t s = (uint32_t)__cvta_generic_to_shared(
                &Bs[buf][row][(ch ^ ((row & 3) << 1)) * 4]);
            cp16(s, B + (size_t)(kk + row) * 128 + ch * 4);
        }
        asm volatile("cp.async.commit_group;");
    };

    load_tile(0, 0);
    int buf = 0;
    for (int kt = 0; kt < 4; ++kt) {
        if (kt + 1 < 4) {
            load_tile(kt + 1, buf ^ 1);
            asm volatile("cp.async.wait_group 1;");
        } else {
            asm volatile("cp.async.wait_group 0;");
        }
        __syncthreads();
#pragma unroll
        for (int k8 = 0; k8 < 4; k8++) {
            uint32_t a[4][4];
#pragma unroll
            for (int mt = 0; mt < 4; mt++) {
                int r0 = mt * 16 + grp;
                int r1 = r0 + 8;
                int sw = grp;
                a[mt][0] = f2tf(As[buf][r0][((2 * k8) ^ sw) * 4 + th4]);
                a[mt][1] = f2tf(As[buf][r1][((2 * k8) ^ sw) * 4 + th4]);
                a[mt][2] = f2tf(As[buf][r0][((2 * k8 + 1) ^ sw) * 4 + th4]);
                a[mt][3] = f2tf(As[buf][r1][((2 * k8 + 1) ^ sw) * 4 + th4]);
            }
#pragma unroll
            for (int nt = 0; nt < 4; nt++) {
                int col = wid * 32 + nt * 8 + grp;
                int idx = ((col >> 2) ^ (th4 << 1)) * 4 + (col & 3);
                uint32_t b0 = f2tf(Bs[buf][k8 * 8 + th4][idx]);
                uint32_t b1 = f2tf(Bs[buf][k8 * 8 + th4 + 4][idx]);
#pragma unroll
                for (int mt = 0; mt < 4; mt++) {
                    asm volatile(
                        "mma.sync.aligned.m16n8k8.row.col.f32.tf32.tf32.f32 "
                        "{%0,%1,%2,%3},{%4,%5,%6,%7},{%8,%9},{%0,%1,%2,%3};"
                        : "+f"(c[mt][nt][0]), "+f"(c[mt][nt][1]),
                          "+f"(c[mt][nt][2]), "+f"(c[mt][nt][3])
                        : "r"(a[mt][0]), "r"(a[mt][1]), "r"(a[mt][2]), "r"(a[mt][3]),
                          "r"(b0), "r"(b1));
                }
            }
        }
        __syncthreads();
        buf ^= 1;
    }

#pragma unroll
    for (int mt = 0; mt < 4; mt++) {
#pragma unroll
        for (int nt = 0; nt < 4; nt++) {
            int row = m0 + mt * 16 + grp;
            int col = wid * 32 + nt * 8 + 2 * th4;
            if (mode == 0) {
                *(float2*)&g_h[(size_t)row * 128 + col] =
                    make_float2(c[mt][nt][0], c[mt][nt][1]);
                *(float2*)&g_h[(size_t)(row + 8) * 128 + col] =
                    make_float2(c[mt][nt][2], c[mt][nt][3]);
            } else {  // transposed, pre-rounded to tf32 bits for bigmm B operand
                g_g2t[(size_t)col * 16384 + row] = __uint_as_float(f2tf(c[mt][nt][0]));
                g_g2t[(size_t)(col + 1) * 16384 + row] = __uint_as_float(f2tf(c[mt][nt][1]));
                g_g2t[(size_t)col * 16384 + row + 8] = __uint_as_float(f2tf(c[mt][nt][2]));
                g_g2t[(size_t)(col + 1) * 16384 + row + 8] = __uint_as_float(f2tf(c[mt][nt][3]));
            }
        }
    }
}

// ----------------- attention scores ----------------------------------------
__global__ void __launch_bounds__(256) dots_kernel(const float* __restrict__ a_src,
                                                   const float* __restrict__ a_dst)
{
    int warp = (blockIdx.x * blockDim.x + threadIdx.x) >> 5;
    if (warp >= N_ITEMS) return;
    int lane = threadIdx.x & 31;
    float4 hv = *(const float4*)&g_h[(size_t)warp * 128 + lane * 4];
    float4 s4 = *(const float4*)&a_src[lane * 4];
    float4 d4 = *(const float4*)&a_dst[lane * 4];
    float s1 = hv.x * s4.x + hv.y * s4.y + hv.z * s4.z + hv.w * s4.w;
    float s2 = hv.x * d4.x + hv.y * d4.y + hv.z * d4.z + hv.w * d4.w;
#pragma unroll
    for (int o = 16; o; o >>= 1) {
        s1 += __shfl_xor_sync(0xffffffffu, s1, o);
        s2 += __shfl_xor_sync(0xffffffffu, s2, o);
    }
    if (lane == 0) { g_ssrc[warp] = s1; g_sdst[warp] = s2; }
}

// ----------------- CSR build ------------------------------------------------
__global__ void zero_cnt_kernel()
{
    for (int i = blockIdx.x * blockDim.x + threadIdx.x; i < N_ITEMS;
         i += gridDim.x * blockDim.x)
        g_cnt[i] = 0;
}

__global__ void count_kernel(const int* __restrict__ ei)
{
    int e = blockIdx.x * blockDim.x + threadIdx.x;
    if (e < NEDGE) atomicAdd(&g_cnt[ei[NEDGE + e] & IMASK], 1);
}

__global__ void __launch_bounds__(1024) scan_kernel()
{
    __shared__ int ssum[1024];
    int t = threadIdx.x;
    int base = t * 16;
    int loc[16];
    int s = 0;
#pragma unroll
    for (int i = 0; i < 16; i++) { loc[i] = g_cnt[base + i]; s += loc[i]; }
    ssum[t] = s;
    __syncthreads();
    for (int d = 1; d < 1024; d <<= 1) {
        int v = (t >= d) ? ssum[t - d] : 0;
        __syncthreads();
        ssum[t] += v;
        __syncthreads();
    }
    int run = t ? ssum[t - 1] : 0;
#pragma unroll
    for (int i = 0; i < 16; i++) {
        g_off[base + i] = run;
        g_pos[base + i] = run;
        run += loc[i];
    }
    if (t == 1023) g_off[N_ITEMS] = run;
}

__global__ void scatter_kernel(const int* __restrict__ ei)
{
    int e = blockIdx.x * blockDim.x + threadIdx.x;
    if (e >= NEDGE) return;
    int d = ei[NEDGE + e] & IMASK;
    int p = atomicAdd(&g_pos[d], 1);
    g_esrc[p] = ei[e] & IMASK;
}

// ----------------- GAT gather: warp per target, pipelined --------------------
__global__ void __launch_bounds__(256) gather_kernel(const float* __restrict__ b_gat)
{
    int node = (blockIdx.x * blockDim.x + threadIdx.x) >> 5;
    if (node >= N_ITEMS) return;
    int lane = threadIdx.x & 31;

    float sd = g_sdst[node];
    float w = __expf(leaky(g_ssrc[node] + sd));
    float denom = w;
    float4 hv = *(const float4*)&g_h[(size_t)node * 128 + lane * 4];
    float4 acc = make_float4(w * hv.x, w * hv.y, w * hv.z, w * hv.w);

    int j = g_off[node], end = g_off[node + 1];
    // depth-1 software pipeline: index, score and vector prefetched one ahead
    int s_cur = (j < end) ? g_esrc[j] : 0;
    float ss_cur = g_ssrc[s_cur];
    float4 hv_cur = *(const float4*)&g_h[(size_t)s_cur * 128 + lane * 4];
    for (; j < end; ++j) {
        int s_nxt = (j + 1 < end) ? g_esrc[j + 1] : 0;
        float ss_nxt = g_ssrc[s_nxt];
        float4 hv_nxt = *(const float4*)&g_h[(size_t)s_nxt * 128 + lane * 4];
        float w2 = __expf(leaky(ss_cur + sd));
        denom += w2;
        acc.x += w2 * hv_cur.x; acc.y += w2 * hv_cur.y;
        acc.z += w2 * hv_cur.z; acc.w += w2 * hv_cur.w;
        ss_cur = ss_nxt; hv_cur = hv_nxt;
    }
    float inv = 1.0f / denom;
    float4 bg = *(const float4*)&b_gat[lane * 4];
    float4 outv = make_float4(acc.x * inv + bg.x, acc.y * inv + bg.y,
                              acc.z * inv + bg.z, acc.w * inv + bg.w);
    *(float4*)&g_gat[(size_t)node * 128 + lane * 4] = outv;
}

// ----------------- epilogue: out = leaky(y+y2+b_etn) @ W_lin -----------------
__global__ void __launch_bounds__(256) final_kernel(const float* __restrict__ b_etn,
                                                    const float* __restrict__ W_lin,
                                                    float* __restrict__ out)
{
    __shared__ float Wl[128 * 64];
    __shared__ float yrow[8][128];
    int tid = threadIdx.x;
    for (int i = tid; i < 128 * 64; i += 256) Wl[i] = W_lin[i];
    __syncthreads();

    int warp = tid >> 5, lane = tid & 31;
    int r = blockIdx.x * 8 + warp;
    if (r >= N_NODES) return;

    float4 yv = *(const float4*)&g_y[(size_t)r * 128 + lane * 4];
    float4 y2 = *(const float4*)&g_y2[(size_t)r * 128 + lane * 4];
    float4 bv = *(const float4*)&b_etn[lane * 4];
    yrow[warp][lane * 4 + 0] = leaky(yv.x + y2.x + bv.x);
    yrow[warp][lane * 4 + 1] = leaky(yv.y + y2.y + bv.y);
    yrow[warp][lane * 4 + 2] = leaky(yv.z + y2.z + bv.z);
    yrow[warp][lane * 4 + 3] = leaky(yv.w + y2.w + bv.w);
    __syncwarp();

    float acc0 = 0.f, acc1 = 0.f;
#pragma unroll
    for (int k = 0; k < 128; k++) {
        float yk = yrow[warp][k];
        acc0 += yk * Wl[k * 64 + lane];
        acc1 += yk * Wl[k * 64 + lane + 32];
    }
    out[(size_t)r * 64 + lane] = acc0;
    out[(size_t)r * 64 + lane + 32] = acc1;
}

// ======================================================================
extern "C" void kernel_launch(void* const* d_in, const int* in_sizes, int n_in,
                              void* d_out, int out_size)
{
    const float* x      = (const float*)d_in[0];
    const float* Hm     = (const float*)d_in[1];
    const int*   ei     = (const int*)d_in[2];
    const float* W_gat  = (const float*)d_in[3];
    const float* a_src  = (const float*)d_in[4];
    const float* a_dst  = (const float*)d_in[5];
    const float* b_gat  = (const float*)d_in[6];
    const float* W_etn  = (const float*)d_in[7];
    const float* b_etn  = (const float*)d_in[8];
    const float* W_lin  = (const float*)d_in[9];
    float* out = (float*)d_out;

    cudaFuncSetAttribute(bigmm_kernel,
                         cudaFuncAttributeMaxDynamicSharedMemorySize, SMEM_BIG);

    // 1. h = x @ W_gat
    gemm_tf32_kernel<<<N_ITEMS / 64, 128>>>(x, W_gat, 0);
    // 2. attention dots
    dots_kernel<<<(N_ITEMS * 32) / 256, 256>>>(a_src, a_dst);
    // 3. CSR by dst
    zero_cnt_kernel<<<64, 256>>>();
    count_kernel<<<NEDGE / 256, 256>>>(ei);
    scan_kernel<<<1, 1024>>>();
    scatter_kernel<<<NEDGE / 256, 256>>>(ei);
    // 4. segment softmax + weighted gather
    gather_kernel<<<(N_ITEMS * 32) / 256, 256>>>(b_gat);
    // 5. g2t = (gat_out @ W_etn)^T  (tf32-rounded bits)
    gemm_tf32_kernel<<<N_ITEMS / 64, 128>>>(nullptr, W_etn, 1);
    // 6. Y(+Y2) = H @ g2   (mma.sync, 128x128 tiles, split-K x2)
    bigmm_kernel<<<128, 256, SMEM_BIG>>>(Hm);
    // 7. out = leaky(Y + Y2 + b_etn) @ W_lin
    final_kernel<<<N_NODES / 8, 256>>>(b_etn, W_lin, out);
}

// round 8
// speedup vs baseline: 1.2605x; 1.0380x over previous
#include <cuda_runtime.h>
#include <cuda_fp16.h>
#include <cstdint>

#define N_ITEMS 16384
#define N_NODES 8192
#define HD 128
#define DOUT 64
#define NEDGE 524288
#define IMASK (N_ITEMS - 1)

// ---------------- scratch (device globals; no allocation allowed) ----------
__device__ __align__(128) float g_h[N_ITEMS * HD];      // x @ W_gat
__device__ __align__(128) float g_gat[N_ITEMS * HD];    // GAT output (+b_gat)
__device__ __align__(128) __half g_g2t[HD * N_ITEMS];   // (gat@W_etn)^T as fp16
__device__ __align__(128) float g_y[N_NODES * HD];      // partial K[0:8192)
__device__ __align__(128) float g_y2[N_NODES * HD];     // partial K[8192:16384)
__device__ __align__(128) float g_ssrc[N_ITEMS];
__device__ __align__(128) float g_sdst[N_ITEMS];
__device__ int g_cnt[N_ITEMS];
__device__ int g_off[N_ITEMS + 1];
__device__ int g_pos[N_ITEMS];
__device__ int g_esrc[NEDGE];

__device__ __forceinline__ float leaky(float v) { return v >= 0.f ? v : 0.2f * v; }

__device__ __forceinline__ uint32_t f2tf(float x) {
    uint32_t r;
    asm("cvt.rna.tf32.f32 %0, %1;" : "=r"(r) : "f"(x));
    return r;
}
__device__ __forceinline__ void cp16(uint32_t s, const void* g) {
    asm volatile("cp.async.cg.shared.global [%0], [%1], 16;\n" ::"r"(s), "l"(g));
}
__device__ __forceinline__ uint32_t pack_h2(float lo, float hi) {
    __half2 h = __floats2half2_rn(lo, hi);
    return *(uint32_t*)&h;
}

// ======================================================================
// Big GEMM (fp16 tensor path): Y[8192,128] = H[8192,16384] @ g2[16384,128]
// split-K x2. grid = 128 (64 m-tiles x 2 k-splits), block = 256.
// SMEM half tiles: A [128 rows][32 k], B [128 n][32 k]; 16B-chunk XOR swizzle:
//   chunk c' = c ^ ((row>>1)&3), row stride 64B.
// ======================================================================
#define BSTG 16384            // A(8KB) + B(8KB) per stage
#define SMEM_BIG (1024 + 4 * BSTG)
#define BKT 256               // 8192 / 32 stages

__device__ __forceinline__ int swz_word(int r, int c, int t4) {
    return r * 16 + ((c ^ ((r >> 1) & 3)) << 2) + t4;
}

__global__ void __launch_bounds__(256) bigmm_kernel(const float* __restrict__ A)
{
    extern __shared__ char smraw[];
    char* sm = (char*)(((uintptr_t)smraw + 1023) & ~(uintptr_t)1023);

    const int tid = threadIdx.x;
    const int lane = tid & 31, wid = tid >> 5;
    const int wm = wid & 1, wn = wid >> 1;      // warp tile: rows wm*64, cols wn*32
    const int grp = lane >> 2, th4 = lane & 3;
    const int mtile = blockIdx.x >> 1, ks = blockIdx.x & 1;
    const int m0 = mtile * 128;
    const int k0 = ks * 8192;

    // per-thread loader coords: 2 chunks (id, id+256); chunk = 8 halfs = 16B
    const int r_ld[2] = { tid >> 2, (tid + 256) >> 2 };
    const int c_ld[2] = { tid & 3, tid & 3 };

    float c[4][4][4];
#pragma unroll
    for (int i = 0; i < 4; i++)
#pragma unroll
        for (int j = 0; j < 4; j++)
#pragma unroll
            for (int k = 0; k < 4; k++) c[i][j][k] = 0.f;

    // ---- preload tiles 0..2 (synchronous A, async B) ----
#pragma unroll
    for (int t = 0; t < 3; t++) {
        char* as = sm + t * BSTG;
        char* bs = as + 8192;
        const int kb = k0 + t * 32;
#pragma unroll
        for (int i = 0; i < 2; i++) {
            int r = r_ld[i], cc = c_ld[i];
            int cs = cc ^ ((r >> 1) & 3);
            const float4* src = (const float4*)(A + (size_t)(m0 + r) * 16384 + kb + cc * 8);
            float4 v0 = src[0], v1 = src[1];
            uint4 w = make_uint4(pack_h2(v0.x, v0.y), pack_h2(v0.z, v0.w),
                                 pack_h2(v1.x, v1.y), pack_h2(v1.z, v1.w));
            *(uint4*)(as + r * 64 + cs * 16) = w;
            cp16((uint32_t)__cvta_generic_to_shared(bs + r * 64 + cs * 16),
                 g_g2t + (size_t)r * 16384 + kb + cc * 8);
        }
        asm volatile("cp.async.commit_group;");
    }

    for (int t = 0; t < BKT; ++t) {
        const bool pf = (t + 3 < BKT);
        float4 av[2][2];
        if (pf) {
            char* bs = sm + ((t + 3) & 3) * BSTG + 8192;
            const int kb = k0 + (t + 3) * 32;
#pragma unroll
            for (int i = 0; i < 2; i++) {
                int r = r_ld[i], cc = c_ld[i];
                int cs = cc ^ ((r >> 1) & 3);
                const float4* src =
                    (const float4*)(A + (size_t)(m0 + r) * 16384 + kb + cc * 8);
                av[i][0] = src[0];
                av[i][1] = src[1];
                cp16((uint32_t)__cvta_generic_to_shared(bs + r * 64 + cs * 16),
                     g_g2t + (size_t)r * 16384 + kb + cc * 8);
            }
        }
        asm volatile("cp.async.commit_group;");
        asm volatile("cp.async.wait_group 3;");
        __syncthreads();

        const uint32_t* as = (const uint32_t*)(sm + (t & 3) * BSTG);
        const uint32_t* bs = as + 2048;
#pragma unroll
        for (int kk = 0; kk < 2; kk++) {      // two k16 steps
            uint32_t a[4][4], b[4][2];
#pragma unroll
            for (int mt = 0; mt < 4; mt++) {
                int r0 = wm * 64 + mt * 16 + grp;
                a[mt][0] = as[swz_word(r0, 2 * kk, th4)];
                a[mt][1] = as[swz_word(r0 + 8, 2 * kk, th4)];
                a[mt][2] = as[swz_word(r0, 2 * kk + 1, th4)];
                a[mt][3] = as[swz_word(r0 + 8, 2 * kk + 1, th4)];
            }
#pragma unroll
            for (int nt = 0; nt < 4; nt++) {
                int cn = wn * 32 + nt * 8 + grp;
                b[nt][0] = bs[swz_word(cn, 2 * kk, th4)];
                b[nt][1] = bs[swz_word(cn, 2 * kk + 1, th4)];
            }
#pragma unroll
            for (int nt = 0; nt < 4; nt++)
#pragma unroll
                for (int mt = 0; mt < 4; mt++) {
                    asm volatile(
                        "mma.sync.aligned.m16n8k16.row.col.f32.f16.f16.f32 "
                        "{%0,%1,%2,%3},{%4,%5,%6,%7},{%8,%9},{%0,%1,%2,%3};"
                        : "+f"(c[mt][nt][0]), "+f"(c[mt][nt][1]),
                          "+f"(c[mt][nt][2]), "+f"(c[mt][nt][3])
                        : "r"(a[mt][0]), "r"(a[mt][1]), "r"(a[mt][2]), "r"(a[mt][3]),
                          "r"(b[nt][0]), "r"(b[nt][1]));
                }
        }
        if (pf) {   // deferred A convert+store (LDG latency overlapped with mma)
            char* asd = sm + ((t + 3) & 3) * BSTG;
#pragma unroll
            for (int i = 0; i < 2; i++) {
                int r = r_ld[i], cc = c_ld[i];
                int cs = cc ^ ((r >> 1) & 3);
                uint4 w = make_uint4(pack_h2(av[i][0].x, av[i][0].y),
                                     pack_h2(av[i][0].z, av[i][0].w),
                                     pack_h2(av[i][1].x, av[i][1].y),
                                     pack_h2(av[i][1].z, av[i][1].w));
                *(uint4*)(asd + r * 64 + cs * 16) = w;
            }
        }
        __syncthreads();
    }

    float* Y = ks ? g_y2 : g_y;
#pragma unroll
    for (int mt = 0; mt < 4; mt++) {
#pragma unroll
        for (int nt = 0; nt < 4; nt++) {
            int row = m0 + wm * 64 + mt * 16 + grp;
            int col = wn * 32 + nt * 8 + 2 * th4;
            *(float2*)&Y[(size_t)row * 128 + col] =
                make_float2(c[mt][nt][0], c[mt][nt][1]);
            *(float2*)&Y[(size_t)(row + 8) * 128 + col] =
                make_float2(c[mt][nt][2], c[mt][nt][3]);
        }
    }
}

// ======================================================================
// small tf32 GEMM (mma.sync): C[M,128] = A[M,K] @ B[K,128], K=128
// mode 0: A=x, B=W_gat -> g_h   (also zeroes g_cnt)
// mode 1: A=g_gat, B=W_etn -> g_g2t (transposed, fp16)
// ======================================================================
__global__ void __launch_bounds__(128) gemm_tf32_kernel(
    const float* __restrict__ Aext, const float* __restrict__ Bext, int mode)
{
    __shared__ float As[2][64][32];
    __shared__ float Bs[2][32][128];

    if (mode == 0) {   // fused g_cnt zeroing (grid 256*128 = 32768 >= N_ITEMS)
        int gt = blockIdx.x * 128 + threadIdx.x;
        if (gt < N_ITEMS) g_cnt[gt] = 0;
    }

    const float* A = (mode == 1) ? g_gat : Aext;
    const float* B = Bext;

    const int tid = threadIdx.x;
    const int lane = tid & 31, wid = tid >> 5;
    const int grp = lane >> 2, th4 = lane & 3;
    const int m0 = blockIdx.x * 64;

    float c[4][4][4];
#pragma unroll
    for (int i = 0; i < 4; i++)
#pragma unroll
        for (int j = 0; j < 4; j++)
#pragma unroll
            for (int k = 0; k < 4; k++) c[i][j][k] = 0.f;

    auto load_tile = [&](int kt, int buf) {
        const int kk = kt * 32;
#pragma unroll
        for (int j = 0; j < 4; j++) {
            int i = tid + j * 128;
            int row = i >> 3, ch = i & 7;
            uint32_t s = (uint32_t)__cvta_generic_to_shared(
                &As[buf][row][(ch ^ (row & 7)) * 4]);
            cp16(s, A + (size_t)(m0 + row) * 128 + kk + ch * 4);
        }
#pragma unroll
        for (int j = 0; j < 8; j++) {
            int i = tid + j * 128;
            int row = i >> 5, ch = i & 31;
            uint32_t s = (uint32_t)__cvta_generic_to_shared(
                &Bs[buf][row][(ch ^ ((row & 3) << 1)) * 4]);
            cp16(s, B + (size_t)(kk + row) * 128 + ch * 4);
        }
        asm volatile("cp.async.commit_group;");
    };

    load_tile(0, 0);
    int buf = 0;
    for (int kt = 0; kt < 4; ++kt) {
        if (kt + 1 < 4) {
            load_tile(kt + 1, buf ^ 1);
            asm volatile("cp.async.wait_group 1;");
        } else {
            asm volatile("cp.async.wait_group 0;");
        }
        __syncthreads();
#pragma unroll
        for (int k8 = 0; k8 < 4; k8++) {
            uint32_t a[4][4];
#pragma unroll
            for (int mt = 0; mt < 4; mt++) {
                int r0 = mt * 16 + grp;
                int r1 = r0 + 8;
                int sw = grp;
                a[mt][0] = f2tf(As[buf][r0][((2 * k8) ^ sw) * 4 + th4]);
                a[mt][1] = f2tf(As[buf][r1][((2 * k8) ^ sw) * 4 + th4]);
                a[mt][2] = f2tf(As[buf][r0][((2 * k8 + 1) ^ sw) * 4 + th4]);
                a[mt][3] = f2tf(As[buf][r1][((2 * k8 + 1) ^ sw) * 4 + th4]);
            }
#pragma unroll
            for (int nt = 0; nt < 4; nt++) {
                int col = wid * 32 + nt * 8 + grp;
                int idx = ((col >> 2) ^ (th4 << 1)) * 4 + (col & 3);
                uint32_t b0 = f2tf(Bs[buf][k8 * 8 + th4][idx]);
                uint32_t b1 = f2tf(Bs[buf][k8 * 8 + th4 + 4][idx]);
#pragma unroll
                for (int mt = 0; mt < 4; mt++) {
                    asm volatile(
                        "mma.sync.aligned.m16n8k8.row.col.f32.tf32.tf32.f32 "
                        "{%0,%1,%2,%3},{%4,%5,%6,%7},{%8,%9},{%0,%1,%2,%3};"
                        : "+f"(c[mt][nt][0]), "+f"(c[mt][nt][1]),
                          "+f"(c[mt][nt][2]), "+f"(c[mt][nt][3])
                        : "r"(a[mt][0]), "r"(a[mt][1]), "r"(a[mt][2]), "r"(a[mt][3]),
                          "r"(b0), "r"(b1));
                }
            }
        }
        __syncthreads();
        buf ^= 1;
    }

#pragma unroll
    for (int mt = 0; mt < 4; mt++) {
#pragma unroll
        for (int nt = 0; nt < 4; nt++) {
            int row = m0 + mt * 16 + grp;
            int col = wid * 32 + nt * 8 + 2 * th4;
            if (mode == 0) {
                *(float2*)&g_h[(size_t)row * 128 + col] =
                    make_float2(c[mt][nt][0], c[mt][nt][1]);
                *(float2*)&g_h[(size_t)(row + 8) * 128 + col] =
                    make_float2(c[mt][nt][2], c[mt][nt][3]);
            } else {  // transposed fp16 for bigmm B operand
                g_g2t[(size_t)col * 16384 + row] = __float2half_rn(c[mt][nt][0]);
                g_g2t[(size_t)(col + 1) * 16384 + row] = __float2half_rn(c[mt][nt][1]);
                g_g2t[(size_t)col * 16384 + row + 8] = __float2half_rn(c[mt][nt][2]);
                g_g2t[(size_t)(col + 1) * 16384 + row + 8] = __float2half_rn(c[mt][nt][3]);
            }
        }
    }
}

// ----------------- attention scores + fused edge count ---------------------
__global__ void __launch_bounds__(256) dots_count_kernel(
    const float* __restrict__ a_src, const float* __restrict__ a_dst,
    const int* __restrict__ ei)
{
    int gt = blockIdx.x * blockDim.x + threadIdx.x;   // 0..524287 == NEDGE
    atomicAdd(&g_cnt[ei[NEDGE + gt] & IMASK], 1);

    int warp = gt >> 5;
    int lane = threadIdx.x & 31;
    float4 hv = *(const float4*)&g_h[(size_t)warp * 128 + lane * 4];
    float4 s4 = *(const float4*)&a_src[lane * 4];
    float4 d4 = *(const float4*)&a_dst[lane * 4];
    float s1 = hv.x * s4.x + hv.y * s4.y + hv.z * s4.z + hv.w * s4.w;
    float s2 = hv.x * d4.x + hv.y * d4.y + hv.z * d4.z + hv.w * d4.w;
#pragma unroll
    for (int o = 16; o; o >>= 1) {
        s1 += __shfl_xor_sync(0xffffffffu, s1, o);
        s2 += __shfl_xor_sync(0xffffffffu, s2, o);
    }
    if (lane == 0) { g_ssrc[warp] = s1; g_sdst[warp] = s2; }
}

// ----------------- CSR scan + scatter ---------------------------------------
__global__ void __launch_bounds__(1024) scan_kernel()
{
    __shared__ int ssum[1024];
    int t = threadIdx.x;
    int base = t * 16;
    int loc[16];
    int s = 0;
#pragma unroll
    for (int i = 0; i < 16; i++) { loc[i] = g_cnt[base + i]; s += loc[i]; }
    ssum[t] = s;
    __syncthreads();
    for (int d = 1; d < 1024; d <<= 1) {
        int v = (t >= d) ? ssum[t - d] : 0;
        __syncthreads();
        ssum[t] += v;
        __syncthreads();
    }
    int run = t ? ssum[t - 1] : 0;
#pragma unroll
    for (int i = 0; i < 16; i++) {
        g_off[base + i] = run;
        g_pos[base + i] = run;
        run += loc[i];
    }
    if (t == 1023) g_off[N_ITEMS] = run;
}

__global__ void scatter_kernel(const int* __restrict__ ei)
{
    int e = blockIdx.x * blockDim.x + threadIdx.x;
    if (e >= NEDGE) return;
    int d = ei[NEDGE + e] & IMASK;
    int p = atomicAdd(&g_pos[d], 1);
    g_esrc[p] = ei[e] & IMASK;
}

// ----------------- GAT gather: warp per target, pipelined --------------------
__global__ void __launch_bounds__(256) gather_kernel(const float* __restrict__ b_gat)
{
    int node = (blockIdx.x * blockDim.x + threadIdx.x) >> 5;
    if (node >= N_ITEMS) return;
    int lane = threadIdx.x & 31;

    float sd = g_sdst[node];
    float w = __expf(leaky(g_ssrc[node] + sd));
    float denom = w;
    float4 hv = *(const float4*)&g_h[(size_t)node * 128 + lane * 4];
    float4 acc = make_float4(w * hv.x, w * hv.y, w * hv.z, w * hv.w);

    int j = g_off[node], end = g_off[node + 1];
    int s_cur = (j < end) ? g_esrc[j] : 0;
    float ss_cur = g_ssrc[s_cur];
    float4 hv_cur = *(const float4*)&g_h[(size_t)s_cur * 128 + lane * 4];
    for (; j < end; ++j) {
        int s_nxt = (j + 1 < end) ? g_esrc[j + 1] : 0;
        float ss_nxt = g_ssrc[s_nxt];
        float4 hv_nxt = *(const float4*)&g_h[(size_t)s_nxt * 128 + lane * 4];
        float w2 = __expf(leaky(ss_cur + sd));
        denom += w2;
        acc.x += w2 * hv_cur.x; acc.y += w2 * hv_cur.y;
        acc.z += w2 * hv_cur.z; acc.w += w2 * hv_cur.w;
        ss_cur = ss_nxt; hv_cur = hv_nxt;
    }
    float inv = 1.0f / denom;
    float4 bg = *(const float4*)&b_gat[lane * 4];
    float4 outv = make_float4(acc.x * inv + bg.x, acc.y * inv + bg.y,
                              acc.z * inv + bg.z, acc.w * inv + bg.w);
    *(float4*)&g_gat[(size_t)node * 128 + lane * 4] = outv;
}

// ----------------- epilogue: out = leaky(y+y2+b_etn) @ W_lin -----------------
__global__ void __launch_bounds__(256) final_kernel(const float* __restrict__ b_etn,
                                                    const float* __restrict__ W_lin,
                                                    float* __restrict__ out)
{
    __shared__ float Wl[128 * 64];
    __shared__ float yrow[8][128];
    int tid = threadIdx.x;
    for (int i = tid; i < 128 * 64; i += 256) Wl[i] = W_lin[i];
    __syncthreads();

    int warp = tid >> 5, lane = tid & 31;
    int r = blockIdx.x * 8 + warp;
    if (r >= N_NODES) return;

    float4 yv = *(const float4*)&g_y[(size_t)r * 128 + lane * 4];
    float4 y2 = *(const float4*)&g_y2[(size_t)r * 128 + lane * 4];
    float4 bv = *(const float4*)&b_etn[lane * 4];
    yrow[warp][lane * 4 + 0] = leaky(yv.x + y2.x + bv.x);
    yrow[warp][lane * 4 + 1] = leaky(yv.y + y2.y + bv.y);
    yrow[warp][lane * 4 + 2] = leaky(yv.z + y2.z + bv.z);
    yrow[warp][lane * 4 + 3] = leaky(yv.w + y2.w + bv.w);
    __syncwarp();

    float acc0 = 0.f, acc1 = 0.f;
#pragma unroll
    for (int k = 0; k < 128; k++) {
        float yk = yrow[warp][k];
        acc0 += yk * Wl[k * 64 + lane];
        acc1 += yk * Wl[k * 64 + lane + 32];
    }
    out[(size_t)r * 64 + lane] = acc0;
    out[(size_t)r * 64 + lane + 32] = acc1;
}

// ======================================================================
extern "C" void kernel_launch(void* const* d_in, const int* in_sizes, int n_in,
                              void* d_out, int out_size)
{
    const float* x      = (const float*)d_in[0];
    const float* Hm     = (const float*)d_in[1];
    const int*   ei     = (const int*)d_in[2];
    const float* W_gat  = (const float*)d_in[3];
    const float* a_src  = (const float*)d_in[4];
    const float* a_dst  = (const float*)d_in[5];
    const float* b_gat  = (const float*)d_in[6];
    const float* W_etn  = (const float*)d_in[7];
    const float* b_etn  = (const float*)d_in[8];
    const float* W_lin  = (const float*)d_in[9];
    float* out = (float*)d_out;

    cudaFuncSetAttribute(bigmm_kernel,
                         cudaFuncAttributeMaxDynamicSharedMemorySize, SMEM_BIG);

    // 1. h = x @ W_gat  (+ zero g_cnt)
    gemm_tf32_kernel<<<N_ITEMS / 64, 128>>>(x, W_gat, 0);
    // 2. attention dots + edge count
    dots_count_kernel<<<NEDGE / 256, 256>>>(a_src, a_dst, ei);
    // 3. CSR scan + scatter
    scan_kernel<<<1, 1024>>>();
    scatter_kernel<<<NEDGE / 256, 256>>>(ei);
    // 4. segment softmax + weighted gather
    gather_kernel<<<(N_ITEMS * 32) / 256, 256>>>(b_gat);
    // 5. g2t = (gat_out @ W_etn)^T  (fp16)
    gemm_tf32_kernel<<<N_ITEMS / 64, 128>>>(nullptr, W_etn, 1);
    // 6. Y(+Y2) = H @ g2   (fp16 mma.sync, 128x128 tiles, split-K x2)
    bigmm_kernel<<<128, 256, SMEM_BIG>>>(Hm);
    // 7. out = leaky(Y + Y2 + b_etn) @ W_lin
    final_kernel<<<N_NODES / 8, 256>>>(b_etn, W_lin, out);
}

// round 9
// speedup vs baseline: 1.3740x; 1.0900x over previous
#include <cuda_runtime.h>
#include <cuda_fp16.h>
#include <cstdint>

#define N_ITEMS 16384
#define N_NODES 8192
#define HD 128
#define DOUT 64
#define NEDGE 524288
#define IMASK (N_ITEMS - 1)

// ---------------- scratch (device globals; no allocation allowed) ----------
__device__ __align__(128) float g_h[N_ITEMS * HD];      // x @ W_gat
__device__ __align__(128) float g_gat[N_ITEMS * HD];    // GAT output (+b_gat)
__device__ __align__(128) __half g_g2t[HD * N_ITEMS];   // (gat@W_etn)^T as fp16
__device__ __align__(128) float g_y[N_NODES * HD];      // partial K[0:8192)
__device__ __align__(128) float g_y2[N_NODES * HD];     // partial K[8192:16384)
__device__ __align__(128) float g_ssrc[N_ITEMS];
__device__ __align__(128) float g_sdst[N_ITEMS];
__device__ int g_cnt[N_ITEMS];
__device__ int g_off[N_ITEMS + 1];
__device__ int g_pos[N_ITEMS];
__device__ int g_esrc[NEDGE];

__device__ __forceinline__ float leaky(float v) { return v >= 0.f ? v : 0.2f * v; }

__device__ __forceinline__ uint32_t f2tf(float x) {
    uint32_t r;
    asm("cvt.rna.tf32.f32 %0, %1;" : "=r"(r) : "f"(x));
    return r;
}
__device__ __forceinline__ void cp16(uint32_t s, const void* g) {
    asm volatile("cp.async.cg.shared.global [%0], [%1], 16;\n" ::"r"(s), "l"(g));
}
__device__ __forceinline__ uint32_t pack_h2(float lo, float hi) {
    __half2 h = __floats2half2_rn(lo, hi);
    return *(uint32_t*)&h;
}
__device__ __forceinline__ uint32_t smem_u32(const void* p) {
    uint32_t a;
    asm("{ .reg .u64 t; cvta.to.shared.u64 t, %1; cvt.u32.u64 %0, t; }" : "=r"(a) : "l"(p));
    return a;
}
__device__ __forceinline__ void ldsm4(uint32_t& r0, uint32_t& r1, uint32_t& r2,
                                      uint32_t& r3, uint32_t a) {
    asm volatile("ldmatrix.sync.aligned.m8n8.x4.shared.b16 {%0,%1,%2,%3}, [%4];"
                 : "=r"(r0), "=r"(r1), "=r"(r2), "=r"(r3) : "r"(a));
}
__device__ __forceinline__ void ldsm2(uint32_t& r0, uint32_t& r1, uint32_t a) {
    asm volatile("ldmatrix.sync.aligned.m8n8.x2.shared.b16 {%0,%1}, [%2];"
                 : "=r"(r0), "=r"(r1) : "r"(a));
}

// ======================================================================
// Big GEMM (fp16 mma, fully cp.async-pipelined):
//   Y[8192,128] = H[8192,16384] @ g2[16384,128], split-K x2.
// grid = 128 (64 m-tiles x 2 k-splits), block = 256 (8 warps, tile 64x32).
// Rings: A32 (f32 via cp.async, 4 stages) -> convert 1 stage ahead -> A16
// (2 stages); B16 (fp16 via cp.async, 4 stages). ldmatrix fragment loads.
// fp16 tiles: row = 32 halfs = 64B = 4 chunks; chunk swizzle c^( (row>>1)&3 ).
// ======================================================================
#define A32_OFF 0                      // 4 x 16384
#define B16_OFF 65536                  // 4 x 8192
#define A16_OFF 98304                  // 2 x 8192
#define SMEM_BIG (114688 + 1024)
#define BKT 256                        // 8192 / 32 k-chunks

__global__ void __launch_bounds__(256) bigmm_kernel(const float* __restrict__ A)
{
    extern __shared__ char smraw[];
    char* sm = (char*)(((uintptr_t)smraw + 1023) & ~(uintptr_t)1023);
    const uint32_t sb = smem_u32(sm);

    const int tid = threadIdx.x;
    const int lane = tid & 31, wid = tid >> 5;
    const int wm = wid & 1, wn = wid >> 1;      // warp tile: rows wm*64, cols wn*32
    const int grp = lane >> 2, th4 = lane & 3;
    const int mtile = blockIdx.x >> 1, ks = blockIdx.x & 1;
    const int m0 = mtile * 128;
    const int k0 = ks * 8192;

    // ldmatrix per-lane address components
    const int rowA = wm * 64 + (lane & 15);          // + mt*16
    const int hiA = lane >> 4;                       // chunk +0/+1
    const int swzA = (rowA >> 1) & 3;
    const int rowB = wn * 32 + (lane & 7);           // + nt*8
    const int hiB = (lane >> 3) & 1;
    const int swzB = (rowB >> 1) & 3;

    float c[4][4][4];
#pragma unroll
    for (int i = 0; i < 4; i++)
#pragma unroll
        for (int j = 0; j < 4; j++)
#pragma unroll
            for (int k = 0; k < 4; k++) c[i][j][k] = 0.f;

    auto issue_cp = [&](int s) {
        char* a32 = sm + A32_OFF + (s & 3) * 16384;
        char* b16 = sm + B16_OFF + (s & 3) * 8192;
        const int kb = k0 + s * 32;
#pragma unroll
        for (int i = 0; i < 4; i++) {       // A32: 1024 chunks (128 rows x 128B)
            int cch = tid + i * 256;
            int r = cch >> 3, ch = cch & 7;
            cp16(sb + A32_OFF + (s & 3) * 16384 + r * 128 + ch * 16,
                 A + (size_t)(m0 + r) * 16384 + kb + ch * 4);
        }
#pragma unroll
        for (int i = 0; i < 2; i++) {       // B16: 512 chunks (128 rows x 64B)
            int cch = tid + i * 256;
            int r = cch >> 2, ch = cch & 3;
            int cs = ch ^ ((r >> 1) & 3);
            cp16(sb + B16_OFF + (s & 3) * 8192 + r * 64 + cs * 16,
                 g_g2t + (size_t)r * 16384 + kb + ch * 8);
        }
        (void)a32; (void)b16;
    };

    auto convert = [&](int s) {             // A32[s&3] -> A16[s&1] (f32 -> fp16 RN)
        const float* a32 = (const float*)(sm + A32_OFF + (s & 3) * 16384);
        char* a16 = sm + A16_OFF + (s & 1) * 8192;
#pragma unroll
        for (int i = 0; i < 2; i++) {
            int c16 = 2 * tid + i;          // fp16 chunk index (512 total)
            int r = c16 >> 2, cc = c16 & 3;
            const float4* src = (const float4*)(a32 + r * 32 + cc * 8);
            float4 v0 = src[0], v1 = src[1];
            uint4 w = make_uint4(pack_h2(v0.x, v0.y), pack_h2(v0.z, v0.w),
                                 pack_h2(v1.x, v1.y), pack_h2(v1.z, v1.w));
            int cs = cc ^ ((r >> 1) & 3);
            *(uint4*)(a16 + r * 64 + cs * 16) = w;
        }
    };

    // ---- prologue: fill 4 stages, convert stage 0 ----
    issue_cp(0); asm volatile("cp.async.commit_group;");
    issue_cp(1); asm volatile("cp.async.commit_group;");
    issue_cp(2); asm volatile("cp.async.commit_group;");
    issue_cp(3); asm volatile("cp.async.commit_group;");
    asm volatile("cp.async.wait_group 3;");
    __syncthreads();
    convert(0);

    for (int t = 0; t < BKT; ++t) {
        asm volatile("cp.async.wait_group 2;");   // stage t+1 landed
        __syncthreads();
        if (t + 1 < BKT) convert(t + 1);

        const uint32_t a16b = sb + A16_OFF + (t & 1) * 8192;
        const uint32_t b16b = sb + B16_OFF + (t & 3) * 8192;
#pragma unroll
        for (int kk = 0; kk < 2; kk++) {
            uint32_t a[4][4], b[4][2];
#pragma unroll
            for (int mt = 0; mt < 4; mt++)
                ldsm4(a[mt][0], a[mt][1], a[mt][2], a[mt][3],
                      a16b + (rowA + mt * 16) * 64 + (((2 * kk + hiA) ^ swzA) << 4));
#pragma unroll
            for (int nt = 0; nt < 4; nt++)
                ldsm2(b[nt][0], b[nt][1],
                      b16b + (rowB + nt * 8) * 64 + (((2 * kk + hiB) ^ swzB) << 4));
#pragma unroll
            for (int nt = 0; nt < 4; nt++)
#pragma unroll
                for (int mt = 0; mt < 4; mt++) {
                    asm volatile(
                        "mma.sync.aligned.m16n8k16.row.col.f32.f16.f16.f32 "
                        "{%0,%1,%2,%3},{%4,%5,%6,%7},{%8,%9},{%0,%1,%2,%3};"
                        : "+f"(c[mt][nt][0]), "+f"(c[mt][nt][1]),
                          "+f"(c[mt][nt][2]), "+f"(c[mt][nt][3])
                        : "r"(a[mt][0]), "r"(a[mt][1]), "r"(a[mt][2]), "r"(a[mt][3]),
                          "r"(b[nt][0]), "r"(b[nt][1]));
                }
        }
        __syncthreads();                         // readers done before ring reuse
        if (t + 4 < BKT) issue_cp(t + 4);
        asm volatile("cp.async.commit_group;");
    }

    float* Y = ks ? g_y2 : g_y;
#pragma unroll
    for (int mt = 0; mt < 4; mt++) {
#pragma unroll
        for (int nt = 0; nt < 4; nt++) {
            int row = m0 + wm * 64 + mt * 16 + grp;
            int col = wn * 32 + nt * 8 + 2 * th4;
            *(float2*)&Y[(size_t)row * 128 + col] =
                make_float2(c[mt][nt][0], c[mt][nt][1]);
            *(float2*)&Y[(size_t)(row + 8) * 128 + col] =
                make_float2(c[mt][nt][2], c[mt][nt][3]);
        }
    }
}

// ======================================================================
// small tf32 GEMM (mma.sync): C[M,128] = A[M,K] @ B[K,128], K=128
// mode 0: A=x, B=W_gat -> g_h   (also zeroes g_cnt)
// mode 1: A=g_gat, B=W_etn -> g_g2t (transposed, fp16)
// ======================================================================
__global__ void __launch_bounds__(128) gemm_tf32_kernel(
    const float* __restrict__ Aext, const float* __restrict__ Bext, int mode)
{
    __shared__ float As[2][64][32];
    __shared__ float Bs[2][32][128];

    if (mode == 0) {   // fused g_cnt zeroing (grid 256 blocks x 128 thr = 32768)
        int gt = blockIdx.x * 128 + threadIdx.x;
        if (gt < N_ITEMS) g_cnt[gt] = 0;
    }

    const float* A = (mode == 1) ? g_gat : Aext;
    const float* B = Bext;

    const int tid = threadIdx.x;
    const int lane = tid & 31, wid = tid >> 5;
    const int grp = lane >> 2, th4 = lane & 3;
    const int m0 = blockIdx.x * 64;

    float c[4][4][4];
#pragma unroll
    for (int i = 0; i < 4; i++)
#pragma unroll
        for (int j = 0; j < 4; j++)
#pragma unroll
            for (int k = 0; k < 4; k++) c[i][j][k] = 0.f;

    auto load_tile = [&](int kt, int buf) {
        const int kk = kt * 32;
#pragma unroll
        for (int j = 0; j < 4; j++) {
            int i = tid + j * 128;
            int row = i >> 3, ch = i & 7;
            uint32_t s = (uint32_t)__cvta_generic_to_shared(
                &As[buf][row][(ch ^ (row & 7)) * 4]);
            cp16(s, A + (size_t)(m0 + row) * 128 + kk + ch * 4);
        }
#pragma unroll
        for (int j = 0; j < 8; j++) {
            int i = tid + j * 128;
            int row = i >> 5, ch = i & 31;
            uint32_t s = (uint32_t)__cvta_generic_to_shared(
                &Bs[buf][row][(ch ^ ((row & 3) << 1)) * 4]);
            cp16(s, B + (size_t)(kk + row) * 128 + ch * 4);
        }
        asm volatile("cp.async.commit_group;");
    };

    load_tile(0, 0);
    int buf = 0;
    for (int kt = 0; kt < 4; ++kt) {
        if (kt + 1 < 4) {
            load_tile(kt + 1, buf ^ 1);
            asm volatile("cp.async.wait_group 1;");
        } else {
            asm volatile("cp.async.wait_group 0;");
        }
        __syncthreads();
#pragma unroll
        for (int k8 = 0; k8 < 4; k8++) {
            uint32_t a[4][4];
#pragma unroll
            for (int mt = 0; mt < 4; mt++) {
                int r0 = mt * 16 + grp;
                int r1 = r0 + 8;
                int sw = grp;
                a[mt][0] = f2tf(As[buf][r0][((2 * k8) ^ sw) * 4 + th4]);
                a[mt][1] = f2tf(As[buf][r1][((2 * k8) ^ sw) * 4 + th4]);
                a[mt][2] = f2tf(As[buf][r0][((2 * k8 + 1) ^ sw) * 4 + th4]);
                a[mt][3] = f2tf(As[buf][r1][((2 * k8 + 1) ^ sw) * 4 + th4]);
            }
#pragma unroll
            for (int nt = 0; nt < 4; nt++) {
                int col = wid * 32 + nt * 8 + grp;
                int idx = ((col >> 2) ^ (th4 << 1)) * 4 + (col & 3);
                uint32_t b0 = f2tf(Bs[buf][k8 * 8 + th4][idx]);
                uint32_t b1 = f2tf(Bs[buf][k8 * 8 + th4 + 4][idx]);
#pragma unroll
                for (int mt = 0; mt < 4; mt++) {
                    asm volatile(
                        "mma.sync.aligned.m16n8k8.row.col.f32.tf32.tf32.f32 "
                        "{%0,%1,%2,%3},{%4,%5,%6,%7},{%8,%9},{%0,%1,%2,%3};"
                        : "+f"(c[mt][nt][0]), "+f"(c[mt][nt][1]),
                          "+f"(c[mt][nt][2]), "+f"(c[mt][nt][3])
                        : "r"(a[mt][0]), "r"(a[mt][1]), "r"(a[mt][2]), "r"(a[mt][3]),
                          "r"(b0), "r"(b1));
                }
            }
        }
        __syncthreads();
        buf ^= 1;
    }

#pragma unroll
    for (int mt = 0; mt < 4; mt++) {
#pragma unroll
        for (int nt = 0; nt < 4; nt++) {
            int row = m0 + mt * 16 + grp;
            int col = wid * 32 + nt * 8 + 2 * th4;
            if (mode == 0) {
                *(float2*)&g_h[(size_t)row * 128 + col] =
                    make_float2(c[mt][nt][0], c[mt][nt][1]);
                *(float2*)&g_h[(size_t)(row + 8) * 128 + col] =
                    make_float2(c[mt][nt][2], c[mt][nt][3]);
            } else {  // transposed fp16 for bigmm B operand
                g_g2t[(size_t)col * 16384 + row] = __float2half_rn(c[mt][nt][0]);
                g_g2t[(size_t)(col + 1) * 16384 + row] = __float2half_rn(c[mt][nt][1]);
                g_g2t[(size_t)col * 16384 + row + 8] = __float2half_rn(c[mt][nt][2]);
                g_g2t[(size_t)(col + 1) * 16384 + row + 8] = __float2half_rn(c[mt][nt][3]);
            }
        }
    }
}

// ----------------- attention scores + fused edge count ---------------------
__global__ void __launch_bounds__(256) dots_count_kernel(
    const float* __restrict__ a_src, const float* __restrict__ a_dst,
    const int* __restrict__ ei)
{
    int gt = blockIdx.x * blockDim.x + threadIdx.x;   // 0..NEDGE-1
    atomicAdd(&g_cnt[ei[NEDGE + gt] & IMASK], 1);

    int warp = gt >> 5;
    int lane = threadIdx.x & 31;
    float4 hv = *(const float4*)&g_h[(size_t)warp * 128 + lane * 4];
    float4 s4 = *(const float4*)&a_src[lane * 4];
    float4 d4 = *(const float4*)&a_dst[lane * 4];
    float s1 = hv.x * s4.x + hv.y * s4.y + hv.z * s4.z + hv.w * s4.w;
    float s2 = hv.x * d4.x + hv.y * d4.y + hv.z * d4.z + hv.w * d4.w;
#pragma unroll
    for (int o = 16; o; o >>= 1) {
        s1 += __shfl_xor_sync(0xffffffffu, s1, o);
        s2 += __shfl_xor_sync(0xffffffffu, s2, o);
    }
    if (lane == 0) { g_ssrc[warp] = s1; g_sdst[warp] = s2; }
}

// ----------------- CSR scan + scatter ---------------------------------------
__global__ void __launch_bounds__(1024) scan_kernel()
{
    __shared__ int ssum[1024];
    int t = threadIdx.x;
    int base = t * 16;
    int loc[16];
    int s = 0;
#pragma unroll
    for (int i = 0; i < 16; i++) { loc[i] = g_cnt[base + i]; s += loc[i]; }
    ssum[t] = s;
    __syncthreads();
    for (int d = 1; d < 1024; d <<= 1) {
        int v = (t >= d) ? ssum[t - d] : 0;
        __syncthreads();
        ssum[t] += v;
        __syncthreads();
    }
    int run = t ? ssum[t - 1] : 0;
#pragma unroll
    for (int i = 0; i < 16; i++) {
        g_off[base + i] = run;
        g_pos[base + i] = run;
        run += loc[i];
    }
    if (t == 1023) g_off[N_ITEMS] = run;
}

__global__ void scatter_kernel(const int* __restrict__ ei)
{
    int e = blockIdx.x * blockDim.x + threadIdx.x;
    if (e >= NEDGE) return;
    int d = ei[NEDGE + e] & IMASK;
    int p = atomicAdd(&g_pos[d], 1);
    g_esrc[p] = ei[e] & IMASK;
}

// ----------------- GAT gather: warp per target, pipelined --------------------
__global__ void __launch_bounds__(256) gather_kernel(const float* __restrict__ b_gat)
{
    int node = (blockIdx.x * blockDim.x + threadIdx.x) >> 5;
    if (node >= N_ITEMS) return;
    int lane = threadIdx.x & 31;

    float sd = g_sdst[node];
    float w = __expf(leaky(g_ssrc[node] + sd));
    float denom = w;
    float4 hv = *(const float4*)&g_h[(size_t)node * 128 + lane * 4];
    float4 acc = make_float4(w * hv.x, w * hv.y, w * hv.z, w * hv.w);

    int j = g_off[node], end = g_off[node + 1];
    int s_cur = (j < end) ? g_esrc[j] : 0;
    float ss_cur = g_ssrc[s_cur];
    float4 hv_cur = *(const float4*)&g_h[(size_t)s_cur * 128 + lane * 4];
    for (; j < end; ++j) {
        int s_nxt = (j + 1 < end) ? g_esrc[j + 1] : 0;
        float ss_nxt = g_ssrc[s_nxt];
        float4 hv_nxt = *(const float4*)&g_h[(size_t)s_nxt * 128 + lane * 4];
        float w2 = __expf(leaky(ss_cur + sd));
        denom += w2;
        acc.x += w2 * hv_cur.x; acc.y += w2 * hv_cur.y;
        acc.z += w2 * hv_cur.z; acc.w += w2 * hv_cur.w;
        ss_cur = ss_nxt; hv_cur = hv_nxt;
    }
    float inv = 1.0f / denom;
    float4 bg = *(const float4*)&b_gat[lane * 4];
    float4 outv = make_float4(acc.x * inv + bg.x, acc.y * inv + bg.y,
                              acc.z * inv + bg.z, acc.w * inv + bg.w);
    *(float4*)&g_gat[(size_t)node * 128 + lane * 4] = outv;
}

// ----------------- epilogue: out = leaky(y+y2+b_etn) @ W_lin -----------------
__global__ void __launch_bounds__(256) final_kernel(const float* __restrict__ b_etn,
                                                    const float* __restrict__ W_lin,
                                                    float* __restrict__ out)
{
    __shared__ float Wl[128 * 64];
    __shared__ float yrow[8][128];
    int tid = threadIdx.x;
    for (int i = tid; i < 128 * 64; i += 256) Wl[i] = W_lin[i];
    __syncthreads();

    int warp = tid >> 5, lane = tid & 31;
    int r = blockIdx.x * 8 + warp;
    if (r >= N_NODES) return;

    float4 yv = *(const float4*)&g_y[(size_t)r * 128 + lane * 4];
    float4 y2 = *(const float4*)&g_y2[(size_t)r * 128 + lane * 4];
    float4 bv = *(const float4*)&b_etn[lane * 4];
    yrow[warp][lane * 4 + 0] = leaky(yv.x + y2.x + bv.x);
    yrow[warp][lane * 4 + 1] = leaky(yv.y + y2.y + bv.y);
    yrow[warp][lane * 4 + 2] = leaky(yv.z + y2.z + bv.z);
    yrow[warp][lane * 4 + 3] = leaky(yv.w + y2.w + bv.w);
    __syncwarp();

    float acc0 = 0.f, acc1 = 0.f;
#pragma unroll
    for (int k = 0; k < 128; k++) {
        float yk = yrow[warp][k];
        acc0 += yk * Wl[k * 64 + lane];
        acc1 += yk * Wl[k * 64 + lane + 32];
    }
    out[(size_t)r * 64 + lane] = acc0;
    out[(size_t)r * 64 + lane + 32] = acc1;
}

// ======================================================================
extern "C" void kernel_launch(void* const* d_in, const int* in_sizes, int n_in,
                              void* d_out, int out_size)
{
    const float* x      = (const float*)d_in[0];
    const float* Hm     = (const float*)d_in[1];
    const int*   ei     = (const int*)d_in[2];
    const float* W_gat  = (const float*)d_in[3];
    const float* a_src  = (const float*)d_in[4];
    const float* a_dst  = (const float*)d_in[5];
    const float* b_gat  = (const float*)d_in[6];
    const float* W_etn  = (const float*)d_in[7];
    const float* b_etn  = (const float*)d_in[8];
    const float* W_lin  = (const float*)d_in[9];
    float* out = (float*)d_out;

    cudaFuncSetAttribute(bigmm_kernel,
                         cudaFuncAttributeMaxDynamicSharedMemorySize, SMEM_BIG);

    // 1. h = x @ W_gat  (+ zero g_cnt)
    gemm_tf32_kernel<<<N_ITEMS / 64, 128>>>(x, W_gat, 0);
    // 2. attention dots + edge count
    dots_count_kernel<<<NEDGE / 256, 256>>>(a_src, a_dst, ei);
    // 3. CSR scan + scatter
    scan_kernel<<<1, 1024>>>();
    scatter_kernel<<<NEDGE / 256, 256>>>(ei);
    // 4. segment softmax + weighted gather
    gather_kernel<<<(N_ITEMS * 32) / 256, 256>>>(b_gat);
    // 5. g2t = (gat_out @ W_etn)^T  (fp16)
    gemm_tf32_kernel<<<N_ITEMS / 64, 128>>>(nullptr, W_etn, 1);
    // 6. Y(+Y2) = H @ g2   (fp16 mma, cp.async-pipelined, ldmatrix, split-K x2)
    bigmm_kernel<<<128, 256, SMEM_BIG>>>(Hm);
    // 7. out = leaky(Y + Y2 + b_etn) @ W_lin
    final_kernel<<<N_NODES / 8, 256>>>(b_etn, W_lin, out);
}

// round 10
// speedup vs baseline: 1.5494x; 1.1276x over previous
#include <cuda_runtime.h>
#include <cuda_fp16.h>
#include <cstdint>

#define N_ITEMS 16384
#define N_NODES 8192
#define HD 128
#define DOUT 64
#define NEDGE 524288
#define IMASK (N_ITEMS - 1)

// ---------------- scratch (device globals; no allocation allowed) ----------
__device__ __align__(128) float g_h[N_ITEMS * HD];       // x @ W_gat
__device__ __align__(128) __half g_gatT[HD * N_ITEMS];   // gat^T fp16 [128][16384]
__device__ __align__(128) float g_y[N_NODES * HD];       // partial K[0:8192)
__device__ __align__(128) float g_y2[N_NODES * HD];      // partial K[8192:16384)
__device__ __align__(128) float g_ssrc[N_ITEMS];
__device__ __align__(128) float g_sdst[N_ITEMS];
__device__ int g_cnt[N_ITEMS];
__device__ int g_off[N_ITEMS + 1];
__device__ int g_pos[N_ITEMS];
__device__ int g_esrc[NEDGE];

__device__ __forceinline__ float leaky(float v) { return v >= 0.f ? v : 0.2f * v; }

__device__ __forceinline__ uint32_t f2tf(float x) {
    uint32_t r;
    asm("cvt.rna.tf32.f32 %0, %1;" : "=r"(r) : "f"(x));
    return r;
}
__device__ __forceinline__ void cp16(uint32_t s, const void* g) {
    asm volatile("cp.async.cg.shared.global [%0], [%1], 16;\n" ::"r"(s), "l"(g));
}
__device__ __forceinline__ uint32_t pack_h2(float lo, float hi) {
    __half2 h = __floats2half2_rn(lo, hi);
    return *(uint32_t*)&h;
}
__device__ __forceinline__ uint32_t smem_u32(const void* p) {
    uint32_t a;
    asm("{ .reg .u64 t; cvta.to.shared.u64 t, %1; cvt.u32.u64 %0, t; }" : "=r"(a) : "l"(p));
    return a;
}
__device__ __forceinline__ void ldsm4(uint32_t& r0, uint32_t& r1, uint32_t& r2,
                                      uint32_t& r3, uint32_t a) {
    asm volatile("ldmatrix.sync.aligned.m8n8.x4.shared.b16 {%0,%1,%2,%3}, [%4];"
                 : "=r"(r0), "=r"(r1), "=r"(r2), "=r"(r3) : "r"(a));
}
__device__ __forceinline__ void ldsm2(uint32_t& r0, uint32_t& r1, uint32_t a) {
    asm volatile("ldmatrix.sync.aligned.m8n8.x2.shared.b16 {%0,%1}, [%2];"
                 : "=r"(r0), "=r"(r1) : "r"(a));
}

// ======================================================================
// Big GEMM (fp16 mma): Y'[8192,128] = H[8192,16384] @ gat[16384,128]
// split-K x2. grid = 128 (64 m-tiles x 2 k-splits), block = 256.
// KC=64 per stage, 128 stages. A32 f32 ring (3 stages) -> convert -> A16
// (2 stages); B16 fp16 ring (3 stages). Rows = 128B = 8 x 16B chunks,
// swizzle chunk c -> c ^ (r & 7)  (conflict-free ldmatrix + STS).
// ======================================================================
#define KC 64
#define KTILES 128
#define A32_OFF 0                       // 3 x 32768
#define B16_OFF 98304                   // 3 x 16384
#define A16_OFF 147456                  // 2 x 16384
#define SMEM_BIG (180224 + 1024)

__global__ void __launch_bounds__(256) bigmm_kernel(const float* __restrict__ A)
{
    extern __shared__ char smraw[];
    char* sm = (char*)(((uintptr_t)smraw + 1023) & ~(uintptr_t)1023);
    const uint32_t sb = smem_u32(sm);

    const int tid = threadIdx.x;
    const int lane = tid & 31, wid = tid >> 5;
    const int wm = wid & 1, wn = wid >> 1;      // warp tile: rows wm*64, cols wn*32
    const int grp = lane >> 2, th4 = lane & 3;
    const int mtile = blockIdx.x >> 1, ks = blockIdx.x & 1;
    const int m0 = mtile * 128;
    const int k0 = ks * 8192;

    const int rowA = wm * 64 + (lane & 15);     // + mt*16
    const int hiA = lane >> 4;
    const int rowB = wn * 32 + (lane & 7);      // + nt*8
    const int hiB = (lane >> 3) & 1;
    const int swz = lane & 7;                   // (row & 7) for both A and B

    float c[4][4][4];
#pragma unroll
    for (int i = 0; i < 4; i++)
#pragma unroll
        for (int j = 0; j < 4; j++)
#pragma unroll
            for (int k = 0; k < 4; k++) c[i][j][k] = 0.f;

    auto issue_cp = [&](int s) {
        const int slot = s % 3;
        const int kb = k0 + s * KC;
#pragma unroll
        for (int i = 0; i < 8; i++) {       // A32: 2048 x 16B (128 rows x 256B)
            int cch = tid + i * 256;
            int r = cch >> 4, cc = cch & 15;
            cp16(sb + A32_OFF + slot * 32768 + r * 256 + cc * 16,
                 A + (size_t)(m0 + r) * 16384 + kb + cc * 4);
        }
#pragma unroll
        for (int i = 0; i < 4; i++) {       // B16: 1024 x 16B (128 rows x 128B)
            int cch = tid + i * 256;
            int r = cch >> 3, oc = cch & 7;
            int cs = oc ^ (r & 7);
            cp16(sb + B16_OFF + slot * 16384 + r * 128 + cs * 16,
                 g_gatT + (size_t)r * 16384 + kb + oc * 8);
        }
    };

    auto convert = [&](int s) {             // A32[s%3] -> A16[s&1]
        const char* a32 = sm + A32_OFF + (s % 3) * 32768;
        char* a16 = sm + A16_OFF + (s & 1) * 16384;
#pragma unroll
        for (int i = 0; i < 4; i++) {
            int j = tid + i * 256;          // fp16 chunk (1024 total)
            int r = j >> 3, oc = j & 7;
            const float4* src = (const float4*)(a32 + r * 256 + oc * 32);
            float4 v0 = src[0], v1 = src[1];
            uint4 w = make_uint4(pack_h2(v0.x, v0.y), pack_h2(v0.z, v0.w),
                                 pack_h2(v1.x, v1.y), pack_h2(v1.z, v1.w));
            *(uint4*)(a16 + r * 128 + ((oc ^ (r & 7)) << 4)) = w;
        }
    };

    issue_cp(0); asm volatile("cp.async.commit_group;");
    issue_cp(1); asm volatile("cp.async.commit_group;");
    issue_cp(2); asm volatile("cp.async.commit_group;");
    asm volatile("cp.async.wait_group 1;");     // stages 0,1 landed
    __syncthreads();
    convert(0);
    __syncthreads();

    for (int t = 0; t < KTILES; ++t) {
        if (t + 1 < KTILES) convert(t + 1);

        const uint32_t a16b = sb + A16_OFF + (t & 1) * 16384;
        const uint32_t b16b = sb + B16_OFF + (t % 3) * 16384;
#pragma unroll
        for (int kk = 0; kk < 4; kk++) {
            uint32_t a[4][4], b[4][2];
#pragma unroll
            for (int mt = 0; mt < 4; mt++)
                ldsm4(a[mt][0], a[mt][1], a[mt][2], a[mt][3],
                      a16b + (rowA + mt * 16) * 128 + (((2 * kk + hiA) ^ swz) << 4));
#pragma unroll
            for (int nt = 0; nt < 4; nt++)
                ldsm2(b[nt][0], b[nt][1],
                      b16b + (rowB + nt * 8) * 128 + (((2 * kk + hiB) ^ swz) << 4));
#pragma unroll
            for (int nt = 0; nt < 4; nt++)
#pragma unroll
                for (int mt = 0; mt < 4; mt++) {
                    asm volatile(
                        "mma.sync.aligned.m16n8k16.row.col.f32.f16.f16.f32 "
                        "{%0,%1,%2,%3},{%4,%5,%6,%7},{%8,%9},{%0,%1,%2,%3};"
                        : "+f"(c[mt][nt][0]), "+f"(c[mt][nt][1]),
                          "+f"(c[mt][nt][2]), "+f"(c[mt][nt][3])
                        : "r"(a[mt][0]), "r"(a[mt][1]), "r"(a[mt][2]), "r"(a[mt][3]),
                          "r"(b[nt][0]), "r"(b[nt][1]));
                }
        }
        __syncthreads();                   // readers done before ring slot reuse
        if (t + 3 < KTILES) issue_cp(t + 3);
        asm volatile("cp.async.commit_group;");
        asm volatile("cp.async.wait_group 1;");   // stage t+2 landed
        __syncthreads();
    }

    float* Y = ks ? g_y2 : g_y;
#pragma unroll
    for (int mt = 0; mt < 4; mt++) {
#pragma unroll
        for (int nt = 0; nt < 4; nt++) {
            int row = m0 + wm * 64 + mt * 16 + grp;
            int col = wn * 32 + nt * 8 + 2 * th4;
            *(float2*)&Y[(size_t)row * 128 + col] =
                make_float2(c[mt][nt][0], c[mt][nt][1]);
            *(float2*)&Y[(size_t)(row + 8) * 128 + col] =
                make_float2(c[mt][nt][2], c[mt][nt][3]);
        }
    }
}

// ======================================================================
// small tf32 GEMM (mma.sync): g_h = x @ W_gat  (K=128); also zeroes g_cnt
// ======================================================================
__global__ void __launch_bounds__(128) gemm0_kernel(
    const float* __restrict__ A, const float* __restrict__ B)
{
    __shared__ float As[2][64][32];
    __shared__ float Bs[2][32][128];

    {   // fused g_cnt zeroing (grid 256 blocks x 128 thr = 32768 >= N_ITEMS)
        int gt = blockIdx.x * 128 + threadIdx.x;
        if (gt < N_ITEMS) g_cnt[gt] = 0;
    }

    const int tid = threadIdx.x;
    const int lane = tid & 31, wid = tid >> 5;
    const int grp = lane >> 2, th4 = lane & 3;
    const int m0 = blockIdx.x * 64;

    float c[4][4][4];
#pragma unroll
    for (int i = 0; i < 4; i++)
#pragma unroll
        for (int j = 0; j < 4; j++)
#pragma unroll
            for (int k = 0; k < 4; k++) c[i][j][k] = 0.f;

    auto load_tile = [&](int kt, int buf) {
        const int kk = kt * 32;
#pragma unroll
        for (int j = 0; j < 4; j++) {
            int i = tid + j * 128;
            int row = i >> 3, ch = i & 7;
            uint32_t s = (uint32_t)__cvta_generic_to_shared(
                &As[buf][row][(ch ^ (row & 7)) * 4]);
            cp16(s, A + (size_t)(m0 + row) * 128 + kk + ch * 4);
        }
#pragma unroll
        for (int j = 0; j < 8; j++) {
            int i = tid + j * 128;
            int row = i >> 5, ch = i & 31;
            uint32_t s = (uint32_t)__cvta_generic_to_shared(
                &Bs[buf][row][(ch ^ ((row & 3) << 1)) * 4]);
            cp16(s, B + (size_t)(kk + row) * 128 + ch * 4);
        }
        asm volatile("cp.async.commit_group;");
    };

    load_tile(0, 0);
    int buf = 0;
    for (int kt = 0; kt < 4; ++kt) {
        if (kt + 1 < 4) {
            load_tile(kt + 1, buf ^ 1);
            asm volatile("cp.async.wait_group 1;");
        } else {
            asm volatile("cp.async.wait_group 0;");
        }
        __syncthreads();
#pragma unroll
        for (int k8 = 0; k8 < 4; k8++) {
            uint32_t a[4][4];
#pragma unroll
            for (int mt = 0; mt < 4; mt++) {
                int r0 = mt * 16 + grp;
                int r1 = r0 + 8;
                int sw = grp;
                a[mt][0] = f2tf(As[buf][r0][((2 * k8) ^ sw) * 4 + th4]);
                a[mt][1] = f2tf(As[buf][r1][((2 * k8) ^ sw) * 4 + th4]);
                a[mt][2] = f2tf(As[buf][r0][((2 * k8 + 1) ^ sw) * 4 + th4]);
                a[mt][3] = f2tf(As[buf][r1][((2 * k8 + 1) ^ sw) * 4 + th4]);
            }
#pragma unroll
            for (int nt = 0; nt < 4; nt++) {
                int col = wid * 32 + nt * 8 + grp;
                int idx = ((col >> 2) ^ (th4 << 1)) * 4 + (col & 3);
                uint32_t b0 = f2tf(Bs[buf][k8 * 8 + th4][idx]);
                uint32_t b1 = f2tf(Bs[buf][k8 * 8 + th4 + 4][idx]);
#pragma unroll
                for (int mt = 0; mt < 4; mt++) {
                    asm volatile(
                        "mma.sync.aligned.m16n8k8.row.col.f32.tf32.tf32.f32 "
                        "{%0,%1,%2,%3},{%4,%5,%6,%7},{%8,%9},{%0,%1,%2,%3};"
                        : "+f"(c[mt][nt][0]), "+f"(c[mt][nt][1]),
                          "+f"(c[mt][nt][2]), "+f"(c[mt][nt][3])
                        : "r"(a[mt][0]), "r"(a[mt][1]), "r"(a[mt][2]), "r"(a[mt][3]),
                          "r"(b0), "r"(b1));
                }
            }
        }
        __syncthreads();
        buf ^= 1;
    }

#pragma unroll
    for (int mt = 0; mt < 4; mt++) {
#pragma unroll
        for (int nt = 0; nt < 4; nt++) {
            int row = m0 + mt * 16 + grp;
            int col = wid * 32 + nt * 8 + 2 * th4;
            *(float2*)&g_h[(size_t)row * 128 + col] =
                make_float2(c[mt][nt][0], c[mt][nt][1]);
            *(float2*)&g_h[(size_t)(row + 8) * 128 + col] =
                make_float2(c[mt][nt][2], c[mt][nt][3]);
        }
    }
}

// ----------------- attention scores + fused edge count ---------------------
__global__ void __launch_bounds__(256) dots_count_kernel(
    const float* __restrict__ a_src, const float* __restrict__ a_dst,
    const int* __restrict__ ei)
{
    int gt = blockIdx.x * blockDim.x + threadIdx.x;   // 0..NEDGE-1
    atomicAdd(&g_cnt[ei[NEDGE + gt] & IMASK], 1);

    int warp = gt >> 5;
    int lane = threadIdx.x & 31;
    float4 hv = *(const float4*)&g_h[(size_t)warp * 128 + lane * 4];
    float4 s4 = *(const float4*)&a_src[lane * 4];
    float4 d4 = *(const float4*)&a_dst[lane * 4];
    float s1 = hv.x * s4.x + hv.y * s4.y + hv.z * s4.z + hv.w * s4.w;
    float s2 = hv.x * d4.x + hv.y * d4.y + hv.z * d4.z + hv.w * d4.w;
#pragma unroll
    for (int o = 16; o; o >>= 1) {
        s1 += __shfl_xor_sync(0xffffffffu, s1, o);
        s2 += __shfl_xor_sync(0xffffffffu, s2, o);
    }
    if (lane == 0) { g_ssrc[warp] = s1; g_sdst[warp] = s2; }
}

// ----------------- CSR scan + scatter ---------------------------------------
__global__ void __launch_bounds__(1024) scan_kernel()
{
    __shared__ int ssum[1024];
    int t = threadIdx.x;
    int base = t * 16;
    int loc[16];
    int s = 0;
#pragma unroll
    for (int i = 0; i < 16; i++) { loc[i] = g_cnt[base + i]; s += loc[i]; }
    ssum[t] = s;
    __syncthreads();
    for (int d = 1; d < 1024; d <<= 1) {
        int v = (t >= d) ? ssum[t - d] : 0;
        __syncthreads();
        ssum[t] += v;
        __syncthreads();
    }
    int run = t ? ssum[t - 1] : 0;
#pragma unroll
    for (int i = 0; i < 16; i++) {
        g_off[base + i] = run;
        g_pos[base + i] = run;
        run += loc[i];
    }
    if (t == 1023) g_off[N_ITEMS] = run;
}

__global__ void scatter_kernel(const int* __restrict__ ei)
{
    int e = blockIdx.x * blockDim.x + threadIdx.x;
    if (e >= NEDGE) return;
    int d = ei[NEDGE + e] & IMASK;
    int p = atomicAdd(&g_pos[d], 1);
    g_esrc[p] = ei[e] & IMASK;
}

// ----------------- GAT gather -> transposed fp16 gat^T -----------------------
__global__ void __launch_bounds__(256) gather_kernel(const float* __restrict__ b_gat)
{
    __shared__ __half sgat[8][128];
    int tid = threadIdx.x;
    int node = (blockIdx.x * 256 + tid) >> 5;
    int lane = tid & 31, warp = tid >> 5;

    float sd = g_sdst[node];
    float w = __expf(leaky(g_ssrc[node] + sd));
    float denom = w;
    float4 hv = *(const float4*)&g_h[(size_t)node * 128 + lane * 4];
    float4 acc = make_float4(w * hv.x, w * hv.y, w * hv.z, w * hv.w);

    int j = g_off[node], end = g_off[node + 1];
    int s_cur = (j < end) ? g_esrc[j] : 0;
    float ss_cur = g_ssrc[s_cur];
    float4 hv_cur = *(const float4*)&g_h[(size_t)s_cur * 128 + lane * 4];
    for (; j < end; ++j) {
        int s_nxt = (j + 1 < end) ? g_esrc[j + 1] : 0;
        float ss_nxt = g_ssrc[s_nxt];
        float4 hv_nxt = *(const float4*)&g_h[(size_t)s_nxt * 128 + lane * 4];
        float w2 = __expf(leaky(ss_cur + sd));
        denom += w2;
        acc.x += w2 * hv_cur.x; acc.y += w2 * hv_cur.y;
        acc.z += w2 * hv_cur.z; acc.w += w2 * hv_cur.w;
        ss_cur = ss_nxt; hv_cur = hv_nxt;
    }
    float inv = 1.0f / denom;
    float4 bg = *(const float4*)&b_gat[lane * 4];
    sgat[warp][lane * 4 + 0] = __float2half_rn(acc.x * inv + bg.x);
    sgat[warp][lane * 4 + 1] = __float2half_rn(acc.y * inv + bg.y);
    sgat[warp][lane * 4 + 2] = __float2half_rn(acc.z * inv + bg.z);
    sgat[warp][lane * 4 + 3] = __float2half_rn(acc.w * inv + bg.w);
    __syncthreads();

    // transpose out: g_gatT[c][node0 .. node0+7]
    int c = tid >> 1, h = tid & 1;
    int node0 = blockIdx.x * 8;
    __half2 p0 = __halves2half2(sgat[h * 4 + 0][c], sgat[h * 4 + 1][c]);
    __half2 p1 = __halves2half2(sgat[h * 4 + 2][c], sgat[h * 4 + 3][c]);
    uint2 v = make_uint2(*(uint32_t*)&p0, *(uint32_t*)&p1);
    *(uint2*)&g_gatT[(size_t)c * 16384 + node0 + h * 4] = v;
}

// ----------------- final: out = leaky((Y'+Y2')@W_etn + b) @ W_lin -----------
#define SMEM_FIN (65536 + 32768 + 4096 + 256)
__global__ void __launch_bounds__(256) final_kernel(const float* __restrict__ W_etn,
                                                    const float* __restrict__ b_etn,
                                                    const float* __restrict__ W_lin,
                                                    float* __restrict__ out)
{
    extern __shared__ char smf[];
    float* We = (float*)smf;                 // [128][128]
    float* Wl = (float*)(smf + 65536);       // [128][64]
    float* zrow = (float*)(smf + 98304);     // [8][128]

    int tid = threadIdx.x;
#pragma unroll
    for (int i = 0; i < 16; i++)
        ((float4*)We)[tid + i * 256] = ((const float4*)W_etn)[tid + i * 256];
#pragma unroll
    for (int i = 0; i < 8; i++)
        ((float4*)Wl)[tid + i * 256] = ((const float4*)W_lin)[tid + i * 256];
    __syncthreads();

    int warp = tid >> 5, lane = tid & 31;
    float4 bv = *(const float4*)&b_etn[lane * 4];

#pragma unroll
    for (int rr = 0; rr < 2; rr++) {
        int r = blockIdx.x * 16 + warp * 2 + rr;
        float4 y1 = *(const float4*)&g_y[(size_t)r * 128 + lane * 4];
        float4 y2 = *(const float4*)&g_y2[(size_t)r * 128 + lane * 4];
        float4 y = make_float4(y1.x + y2.x, y1.y + y2.y, y1.z + y2.z, y1.w + y2.w);

        float4 z = bv;
#pragma unroll
        for (int k4 = 0; k4 < 32; k4++) {
            float4 yv;
            yv.x = __shfl_sync(0xffffffffu, y.x, k4);
            yv.y = __shfl_sync(0xffffffffu, y.y, k4);
            yv.z = __shfl_sync(0xffffffffu, y.z, k4);
            yv.w = __shfl_sync(0xffffffffu, y.w, k4);
            float4 w0 = ((float4*)We)[(k4 * 4 + 0) * 32 + lane];
            z.x += yv.x * w0.x; z.y += yv.x * w0.y; z.z += yv.x * w0.z; z.w += yv.x * w0.w;
            float4 w1 = ((float4*)We)[(k4 * 4 + 1) * 32 + lane];
            z.x += yv.y * w1.x; z.y += yv.y * w1.y; z.z += yv.y * w1.z; z.w += yv.y * w1.w;
            float4 w2 = ((float4*)We)[(k4 * 4 + 2) * 32 + lane];
            z.x += yv.z * w2.x; z.y += yv.z * w2.y; z.z += yv.z * w2.z; z.w += yv.z * w2.w;
            float4 w3 = ((float4*)We)[(k4 * 4 + 3) * 32 + lane];
            z.x += yv.w * w3.x; z.y += yv.w * w3.y; z.z += yv.w * w3.z; z.w += yv.w * w3.w;
        }
        z.x = leaky(z.x); z.y = leaky(z.y); z.z = leaky(z.z); z.w = leaky(z.w);
        *(float4*)&zrow[warp * 128 + lane * 4] = z;
        __syncwarp();

        float o0 = 0.f, o1 = 0.f;
#pragma unroll
        for (int k = 0; k < 128; k++) {
            float zk = zrow[warp * 128 + k];
            float2 w = ((float2*)Wl)[k * 32 + lane];
            o0 += zk * w.x;
            o1 += zk * w.y;
        }
        *(float2*)&out[(size_t)r * 64 + lane * 2] = make_float2(o0, o1);
        __syncwarp();
    }
}

// ======================================================================
extern "C" void kernel_launch(void* const* d_in, const int* in_sizes, int n_in,
                              void* d_out, int out_size)
{
    const float* x      = (const float*)d_in[0];
    const float* Hm     = (const float*)d_in[1];
    const int*   ei     = (const int*)d_in[2];
    const float* W_gat  = (const float*)d_in[3];
    const float* a_src  = (const float*)d_in[4];
    const float* a_dst  = (const float*)d_in[5];
    const float* b_gat  = (const float*)d_in[6];
    const float* W_etn  = (const float*)d_in[7];
    const float* b_etn  = (const float*)d_in[8];
    const float* W_lin  = (const float*)d_in[9];
    float* out = (float*)d_out;

    cudaFuncSetAttribute(bigmm_kernel,
                         cudaFuncAttributeMaxDynamicSharedMemorySize, SMEM_BIG);
    cudaFuncSetAttribute(final_kernel,
                         cudaFuncAttributeMaxDynamicSharedMemorySize, SMEM_FIN);

    // 1. h = x @ W_gat  (+ zero g_cnt)
    gemm0_kernel<<<N_ITEMS / 64, 128>>>(x, W_gat);
    // 2. attention dots + edge count
    dots_count_kernel<<<NEDGE / 256, 256>>>(a_src, a_dst, ei);
    // 3. CSR scan + scatter
    scan_kernel<<<1, 1024>>>();
    scatter_kernel<<<NEDGE / 256, 256>>>(ei);
    // 4. segment softmax + gather -> gat^T (fp16)
    gather_kernel<<<N_ITEMS / 8, 256>>>(b_gat);
    // 5. Y'(+Y2') = H @ gat   (fp16 mma, KC=64 pipeline, split-K x2)
    bigmm_kernel<<<128, 256, SMEM_BIG>>>(Hm);
    // 6. out = leaky((Y'+Y2')@W_etn + b_etn) @ W_lin
    final_kernel<<<N_NODES / 16, 256, SMEM_FIN>>>(W_etn, b_etn, W_lin, out);
}